// round 10
// baseline (speedup 1.0000x reference)
#include <cuda_runtime.h>
#include <cuda_bf16.h>
#include <cstdint>

// Problem dims
#define BATCH 1024
#define TSTEPS 200
#define DDIM 128
#define NROWS (BATCH*TSTEPS)      // 204800 flattened (b,t) rows

#define THREADS 256
#define CLUSTER_SIZE 4
#define MT 32                     // batch rows per cluster

// main-kernel SMEM
#define SM_BHI 0                  // [128 n][512 B]
#define SM_BLO 65536
#define SM_H1  131072             // 16 KB (hi 8K + lo 8K)
#define SM_H2  147456
#define SMEM_MAIN 163840

// pre-GEMM SMEM
#define PG_AHI 0                  // [128 r][256 B]
#define PG_ALO 32768
#define PG_BHI 65536              // [128 n][256 B]
#define PG_BLO 98304
#define SMEM_PRE 131072

// device globals (no allocation allowed)
__device__ __nv_bfloat16 gWUt_hi[512*256];   // [col 512][k 256] transposed split W||U
__device__ __nv_bfloat16 gWUt_lo[512*256];
__device__ float gz1[(size_t)NROWS*512];     // x·W for all t  (~420 MB)
__device__ __nv_bfloat16 gh1[2][BATCH*256];  // [slot][row*256 + plane*128 + cell]
__device__ __nv_bfloat16 gh2[2][BATCH*256];

// ---------------- helpers ----------------
__device__ __forceinline__ uint32_t smem_u32(const void* p){
    uint32_t a;
    asm("{ .reg .u64 t; cvta.to.shared.u64 t, %1; cvt.u32.u64 %0, t; }" : "=r"(a) : "l"(p));
    return a;
}
__device__ __forceinline__ uint32_t cl_rank(){
    uint32_t r; asm("mov.u32 %0, %%cluster_ctarank;" : "=r"(r)); return r;
}
__device__ __forceinline__ void cl_arrive(){ asm volatile("barrier.cluster.arrive.aligned;" ::: "memory"); }
__device__ __forceinline__ void cl_wait(){ asm volatile("barrier.cluster.wait.aligned;" ::: "memory"); }
__device__ __forceinline__ void cpa16(uint32_t dst, const void* src){
    asm volatile("cp.async.cg.shared.global [%0], [%1], 16;" :: "r"(dst), "l"(src));
}
__device__ __forceinline__ void cp_commit(){ asm volatile("cp.async.commit_group;" ::: "memory"); }
template<int N> __device__ __forceinline__ void cp_wait(){ asm volatile("cp.async.wait_group %0;" :: "n"(N) : "memory"); }

__device__ __forceinline__ void ldsm4(uint32_t& r0, uint32_t& r1, uint32_t& r2, uint32_t& r3, uint32_t addr){
    asm volatile("ldmatrix.sync.aligned.m8n8.x4.shared.b16 {%0,%1,%2,%3}, [%4];"
                 : "=r"(r0), "=r"(r1), "=r"(r2), "=r"(r3) : "r"(addr));
}
__device__ __forceinline__ void hmma(float* c, const uint32_t* a, uint32_t b0, uint32_t b1){
    asm volatile("mma.sync.aligned.m16n8k16.row.col.f32.bf16.bf16.f32 "
                 "{%0,%1,%2,%3}, {%4,%5,%6,%7}, {%8,%9}, {%0,%1,%2,%3};"
                 : "+f"(c[0]), "+f"(c[1]), "+f"(c[2]), "+f"(c[3])
                 : "r"(a[0]), "r"(a[1]), "r"(a[2]), "r"(a[3]), "r"(b0), "r"(b1));
}
__device__ __forceinline__ float fsig(float x){ return __fdividef(1.f, 1.f + __expf(-x)); }
__device__ __forceinline__ float ftanh_(float x){
    x = fminf(15.f, fmaxf(-15.f, x));
    float e = __expf(2.f * x);
    return __fdividef(e - 1.f, e + 1.f);
}
__device__ __forceinline__ void split1(float v, __nv_bfloat16& hi, __nv_bfloat16& lo){
    hi = __float2bfloat16(v);
    lo = __float2bfloat16(v - __bfloat162float(hi));
}
__device__ __forceinline__ void split4(float4 v, uint2& hi, uint2& lo){
    __nv_bfloat16 hx, hy, hz, hw, lx, ly, lz, lw;
    split1(v.x, hx, lx); split1(v.y, hy, ly); split1(v.z, hz, lz); split1(v.w, hw, lw);
    __nv_bfloat162 h01; h01.x = hx; h01.y = hy;
    __nv_bfloat162 h23; h23.x = hz; h23.y = hw;
    __nv_bfloat162 l01; l01.x = lx; l01.y = ly;
    __nv_bfloat162 l23; l23.x = lz; l23.y = lw;
    hi.x = *reinterpret_cast<uint32_t*>(&h01); hi.y = *reinterpret_cast<uint32_t*>(&h23);
    lo.x = *reinterpret_cast<uint32_t*>(&l01); lo.y = *reinterpret_cast<uint32_t*>(&l23);
}

// -------- kernel 1: split W||U into transposed bf16 hi/lo table --------
__global__ void __launch_bounds__(256)
split_w_kernel(const float* __restrict__ W, const float* __restrict__ U)
{
    int e0 = (blockIdx.x * 256 + threadIdx.x) * 4;
    #pragma unroll
    for (int j = 0; j < 4; ++j){
        int e = e0 + j;                 // 0..131071
        int n = e >> 8, k = e & 255;
        float v = (k < 128) ? W[k * 512 + n] : U[(k - 128) * 512 + n];
        __nv_bfloat16 hi, lo; split1(v, hi, lo);
        gWUt_hi[n * 256 + k] = hi;
        gWUt_lo[n * 256 + k] = lo;
    }
}

extern __shared__ char smem[];

// -------- kernel 2: z1x = x·W for all timesteps (3xBF16) --------
__global__ void __launch_bounds__(256)
z1x_kernel(const float* __restrict__ x)
{
    const uint32_t sbase = smem_u32(smem);
    const int tid = threadIdx.x;
    const int wid = tid >> 5, lane = tid & 31;
    const int r0 = blockIdx.x * 128;     // flattened (b,t) row
    const int n0 = blockIdx.y * 128;     // output col

    // A: load x fp32 (coalesced), split, store swizzled
    #pragma unroll
    for (int i = 0; i < 16; ++i){
        int idx = tid + i * 256;         // 0..4095
        int r = idx >> 5, q = idx & 31;  // q = float4 within row (128 k)
        float4 v = reinterpret_cast<const float4*>(x)[(size_t)(r0 + r) * 32 + q];
        uint2 hi, lo; split4(v, hi, lo);
        uint32_t off = r * 256 + ((((q >> 1) ^ (r & 7)) << 4)) + ((q & 1) << 3);
        *reinterpret_cast<uint2*>(smem + PG_AHI + off) = hi;
        *reinterpret_cast<uint2*>(smem + PG_ALO + off) = lo;
    }
    // B: cp.async rows (k 0..127 of gWUt = W part)
    #pragma unroll
    for (int i = 0; i < 16; ++i){
        int idx = tid + i * 256;         // 0..4095
        int pl = idx >> 11, rem = idx & 2047;
        int n = rem >> 4, u = rem & 15;
        uint32_t dst = sbase + (pl ? PG_BLO : PG_BHI) + n * 256 + (((u ^ (n & 7)) << 4));
        const __nv_bfloat16* src = (pl ? gWUt_lo : gWUt_hi) + (size_t)(n0 + n) * 256 + u * 8;
        cpa16(dst, src);
    }
    cp_commit();
    cp_wait<0>();
    __syncthreads();

    // warp tile m32 x n64
    const int wm = wid >> 1, wn = wid & 1;
    const int arow0 = wm * 32 + (lane & 15);
    const int arow1 = arow0 + 16;
    const uint32_t a0b = arow0 * 256, a0x = (arow0 & 7) << 4;
    const uint32_t a1b = arow1 * 256, a1x = (arow1 & 7) << 4;
    const uint32_t a_lk = (lane >> 4) << 4;
    int bn[4];
    #pragma unroll
    for (int nfp = 0; nfp < 4; ++nfp)
        bn[nfp] = wn * 64 + nfp * 16 + (lane & 7) + ((lane >> 4) << 3);
    const uint32_t b_lk = ((lane >> 3) & 1) << 4;

    float acc[2][8][4];
    #pragma unroll
    for (int b = 0; b < 2; ++b)
        #pragma unroll
        for (int f = 0; f < 8; ++f)
            #pragma unroll
            for (int j = 0; j < 4; ++j) acc[b][f][j] = 0.f;

    #pragma unroll 4
    for (int ks = 0; ks < 8; ++ks){
        uint32_t ka = ks * 32;
        uint32_t ahi0[4], alo0[4], ahi1[4], alo1[4], bh[16], bl[16];
        ldsm4(ahi0[0], ahi0[1], ahi0[2], ahi0[3], sbase + PG_AHI + a0b + ((ka + a_lk) ^ a0x));
        ldsm4(alo0[0], alo0[1], alo0[2], alo0[3], sbase + PG_ALO + a0b + ((ka + a_lk) ^ a0x));
        ldsm4(ahi1[0], ahi1[1], ahi1[2], ahi1[3], sbase + PG_AHI + a1b + ((ka + a_lk) ^ a1x));
        ldsm4(alo1[0], alo1[1], alo1[2], alo1[3], sbase + PG_ALO + a1b + ((ka + a_lk) ^ a1x));
        #pragma unroll
        for (int nfp = 0; nfp < 4; ++nfp){
            uint32_t ba = bn[nfp] * 256 + ((ka + b_lk) ^ ((uint32_t)(bn[nfp] & 7) << 4));
            ldsm4(bh[nfp*4+0], bh[nfp*4+1], bh[nfp*4+2], bh[nfp*4+3], sbase + PG_BHI + ba);
            ldsm4(bl[nfp*4+0], bl[nfp*4+1], bl[nfp*4+2], bl[nfp*4+3], sbase + PG_BLO + ba);
        }
        #pragma unroll
        for (int nf = 0; nf < 8; ++nf){
            uint32_t bh0 = bh[(nf >> 1) * 4 + (nf & 1) * 2], bh1 = bh[(nf >> 1) * 4 + (nf & 1) * 2 + 1];
            uint32_t bl0 = bl[(nf >> 1) * 4 + (nf & 1) * 2], bl1 = bl[(nf >> 1) * 4 + (nf & 1) * 2 + 1];
            hmma(acc[0][nf], ahi0, bh0, bh1);
            hmma(acc[0][nf], ahi0, bl0, bl1);
            hmma(acc[0][nf], alo0, bh0, bh1);
            hmma(acc[1][nf], ahi1, bh0, bh1);
            hmma(acc[1][nf], ahi1, bl0, bl1);
            hmma(acc[1][nf], alo1, bh0, bh1);
        }
    }

    // epilogue: store fp32
    #pragma unroll
    for (int blk = 0; blk < 2; ++blk)
        #pragma unroll
        for (int nf = 0; nf < 8; ++nf){
            int row = r0 + wm * 32 + blk * 16 + (lane >> 2);
            int col = n0 + wn * 64 + nf * 8 + (lane & 3) * 2;
            float2 v0; v0.x = acc[blk][nf][0]; v0.y = acc[blk][nf][1];
            float2 v1; v1.x = acc[blk][nf][2]; v1.y = acc[blk][nf][3];
            *reinterpret_cast<float2*>(&gz1[(size_t)row * 512 + col]) = v0;
            *reinterpret_cast<float2*>(&gz1[(size_t)(row + 8) * 512 + col]) = v1;
        }
}

// -------- kernel 3: persistent recurrent loop --------
__global__ void __launch_bounds__(THREADS, 1) __cluster_dims__(CLUSTER_SIZE, 1, 1)
lstm_main_kernel(const float* __restrict__ bias, float* __restrict__ out)
{
    const uint32_t sbase = smem_u32(smem);
    const int tid = threadIdx.x;
    const int wid = tid >> 5, lane = tid & 31;
    const uint32_t rank = cl_rank();
    const int m0 = (blockIdx.x >> 2) * MT;

    // ---- B build via cp.async from gWUt: n = gate*32 + cell_local, 512B rows
    #pragma unroll
    for (int i = 0; i < 32; ++i){
        int idx = tid + i * THREADS;     // 0..8191
        int pl = idx >> 12, rem = idx & 4095;
        int n = rem >> 5, u = rem & 31;
        int gate = n >> 5, cell = n & 31;
        int gcol = gate * 128 + (int)rank * 32 + cell;
        uint32_t dst = sbase + (pl ? SM_BLO : SM_BHI) + n * 512 + (((u ^ (n & 7)) << 4));
        const __nv_bfloat16* src = (pl ? gWUt_lo : gWUt_hi) + (size_t)gcol * 256 + u * 8;
        cpa16(dst, src);
    }
    cp_commit();

    // ---- per-warp coordinates (m16 x n32 per warp)
    const int wm = wid & 1, ws = wid >> 1;
    const int a_row = wm * 16 + (lane & 15);
    const uint32_t a_base = a_row * 256;
    const uint32_t a_xor = (a_row & 7) << 4;
    const uint32_t a_lk = (lane >> 4) << 4;
    const int n01 = ws * 8 + (lane & 7) + ((lane >> 4) << 5);
    const int n23 = n01 + 64;
    const uint32_t b01b = n01 * 512, b01x = (n01 & 7) << 4;
    const uint32_t b23b = n23 * 512, b23x = (n23 & 7) << 4;
    const uint32_t b_lk = ((lane >> 3) & 1) << 4;

    const int R = wm * 16 + (lane >> 2);
    const int gc = (int)rank * 32 + ws * 8 + (lane & 3) * 2;

    // ---- zero h2(0) own slice
    {
        __nv_bfloat162 z; z.x = __float2bfloat16(0.f); z.y = z.x;
        #pragma unroll
        for (int rh = 0; rh < 2; ++rh){
            int r = m0 + R + rh * 8;
            *reinterpret_cast<__nv_bfloat162*>(&gh2[0][r * 256 + gc]) = z;
            *reinterpret_cast<__nv_bfloat162*>(&gh2[0][r * 256 + 128 + gc]) = z;
        }
    }
    cp_wait<0>();
    __syncthreads();
    cl_arrive(); cl_wait();

    float bia[4][2];
    #pragma unroll
    for (int g = 0; g < 4; ++g){
        bia[g][0] = bias[g * 128 + gc];
        bia[g][1] = bias[g * 128 + gc + 1];
    }

    float c1[4], c2[4], h1n[4];
    #pragma unroll
    for (int j = 0; j < 4; ++j){ c1[j] = 0.f; c2[j] = 0.f; }

    float acc1[4][4], acc2[4][4];

    #define ACC_INIT(A)                                         \
        _Pragma("unroll")                                       \
        for (int g = 0; g < 4; ++g){                            \
            A[g][0] = bia[g][0]; A[g][1] = bia[g][1];           \
            A[g][2] = bia[g][0]; A[g][3] = bia[g][1];           \
        }

    #define MMA_RANGE(A, AHI, ALO, BOFS, K0, K1)                                       \
    {                                                                                  \
        _Pragma("unroll")                                                              \
        for (int ks = (K0); ks < (K1); ++ks){                                          \
            uint32_t kbA = (uint32_t)(ks * 32) + a_lk;                                 \
            uint32_t kbB = (uint32_t)(ks * 32) + (uint32_t)(BOFS) + b_lk;              \
            uint32_t ahi[4], alo[4], bh[8], bl[8];                                     \
            ldsm4(ahi[0], ahi[1], ahi[2], ahi[3], (AHI) + a_base + (kbA ^ a_xor));     \
            ldsm4(alo[0], alo[1], alo[2], alo[3], (ALO) + a_base + (kbA ^ a_xor));     \
            ldsm4(bh[0], bh[1], bh[2], bh[3], sbase + SM_BHI + b01b + (kbB ^ b01x));   \
            ldsm4(bh[4], bh[5], bh[6], bh[7], sbase + SM_BHI + b23b + (kbB ^ b23x));   \
            ldsm4(bl[0], bl[1], bl[2], bl[3], sbase + SM_BLO + b01b + (kbB ^ b01x));   \
            ldsm4(bl[4], bl[5], bl[6], bl[7], sbase + SM_BLO + b23b + (kbB ^ b23x));   \
            _Pragma("unroll")                                                          \
            for (int g = 0; g < 4; ++g){                                               \
                hmma(A[g], ahi, bh[g*2], bh[g*2+1]);                                   \
                hmma(A[g], ahi, bl[g*2], bl[g*2+1]);                                   \
                hmma(A[g], alo, bh[g*2], bh[g*2+1]);                                   \
            }                                                                          \
        }                                                                              \
    }

    // fused: A = h1(t+1) from H1 buf; U half -> acc1, W half -> acc2
    #define MMA_FUSED(H1B)                                                             \
    {                                                                                  \
        _Pragma("unroll")                                                              \
        for (int ks = 0; ks < 8; ++ks){                                                \
            uint32_t kbA = (uint32_t)(ks * 32) + a_lk;                                 \
            uint32_t kbU = (uint32_t)(ks * 32) + 256u + b_lk;                          \
            uint32_t kbW = (uint32_t)(ks * 32) + b_lk;                                 \
            uint32_t ahi[4], alo[4], bhU[8], blU[8], bhW[8], blW[8];                   \
            ldsm4(ahi[0], ahi[1], ahi[2], ahi[3], (H1B) + a_base + (kbA ^ a_xor));     \
            ldsm4(alo[0], alo[1], alo[2], alo[3], (H1B) + 8192 + a_base + (kbA ^ a_xor)); \
            ldsm4(bhU[0], bhU[1], bhU[2], bhU[3], sbase + SM_BHI + b01b + (kbU ^ b01x)); \
            ldsm4(bhU[4], bhU[5], bhU[6], bhU[7], sbase + SM_BHI + b23b + (kbU ^ b23x)); \
            ldsm4(blU[0], blU[1], blU[2], blU[3], sbase + SM_BLO + b01b + (kbU ^ b01x)); \
            ldsm4(blU[4], blU[5], blU[6], blU[7], sbase + SM_BLO + b23b + (kbU ^ b23x)); \
            ldsm4(bhW[0], bhW[1], bhW[2], bhW[3], sbase + SM_BHI + b01b + (kbW ^ b01x)); \
            ldsm4(bhW[4], bhW[5], bhW[6], bhW[7], sbase + SM_BHI + b23b + (kbW ^ b23x)); \
            ldsm4(blW[0], blW[1], blW[2], blW[3], sbase + SM_BLO + b01b + (kbW ^ b01x)); \
            ldsm4(blW[4], blW[5], blW[6], blW[7], sbase + SM_BLO + b23b + (kbW ^ b23x)); \
            _Pragma("unroll")                                                          \
            for (int g = 0; g < 4; ++g){                                               \
                hmma(acc1[g], ahi, bhU[g*2], bhU[g*2+1]);                              \
                hmma(acc1[g], ahi, blU[g*2], blU[g*2+1]);                              \
                hmma(acc1[g], alo, bhU[g*2], bhU[g*2+1]);                              \
                hmma(acc2[g], ahi, bhW[g*2], bhW[g*2+1]);                              \
                hmma(acc2[g], ahi, blW[g*2], blW[g*2+1]);                              \
                hmma(acc2[g], alo, bhW[g*2], bhW[g*2+1]);                              \
            }                                                                          \
        }                                                                              \
    }

    const uint32_t H1b = sbase + SM_H1, H2b = sbase + SM_H2;

    // prologue: acc1 = bias + z1x(0)  (h1(0) = 0)
    {
        #pragma unroll
        for (int g = 0; g < 4; ++g){
            float2 z0 = *reinterpret_cast<const float2*>(
                &gz1[((size_t)(m0 + R) * TSTEPS + 0) * 512 + g * 128 + gc]);
            float2 z1v = *reinterpret_cast<const float2*>(
                &gz1[((size_t)(m0 + R + 8) * TSTEPS + 0) * 512 + g * 128 + gc]);
            acc1[g][0] = bia[g][0] + z0.x;  acc1[g][1] = bia[g][1] + z0.y;
            acc1[g][2] = bia[g][0] + z1v.x; acc1[g][3] = bia[g][1] + z1v.y;
        }
    }

    for (int t = 0; t < TSTEPS; ++t){
        const int s = t & 1, ns = s ^ 1;

        // ===== E1 =====
        #pragma unroll
        for (int j = 0; j < 4; ++j){
            float cn = fsig(acc1[1][j]) * c1[j] + fsig(acc1[0][j]) * ftanh_(acc1[2][j]);
            c1[j] = cn;
            h1n[j] = fsig(acc1[3][j]) * ftanh_(cn);
        }
        // P1: publish own h1(t+1) slice
        #pragma unroll
        for (int rh = 0; rh < 2; ++rh){
            int r = m0 + R + rh * 8;
            __nv_bfloat162 hh, ll;
            split1(h1n[rh * 2 + 0], hh.x, ll.x);
            split1(h1n[rh * 2 + 1], hh.y, ll.y);
            *reinterpret_cast<__nv_bfloat162*>(&gh1[ns][r * 256 + gc]) = hh;
            *reinterpret_cast<__nv_bfloat162*>(&gh1[ns][r * 256 + 128 + gc]) = ll;
        }

        if (t > 0) cl_wait();    // B_{t-1}: h2(t) visible; buffers reusable

        // Ga: H2buf <- gh2[s]
        #pragma unroll
        for (int i = 0; i < 4; ++i){
            int idx = tid + i * THREADS;
            int pl = idx >> 9, r = (idx >> 4) & 31, u = idx & 15;
            cpa16(H2b + pl * 8192 + r * 256 + (((u ^ (r & 7)) << 4)),
                  &gh2[s][(m0 + r) * 256 + pl * 128 + u * 8]);
        }
        cp_commit();

        cl_arrive();             // A_t (h1(t+1) release)

        // z1x(t+1) loads (clamped at last step; values unused then)
        int tz = (t + 1 < TSTEPS) ? (t + 1) : t;
        float2 zx0[4], zx1[4];
        #pragma unroll
        for (int g = 0; g < 4; ++g){
            zx0[g] = *reinterpret_cast<const float2*>(
                &gz1[((size_t)(m0 + R) * TSTEPS + tz) * 512 + g * 128 + gc]);
            zx1[g] = *reinterpret_cast<const float2*>(
                &gz1[((size_t)(m0 + R + 8) * TSTEPS + tz) * 512 + g * 128 + gc]);
        }

        cp_wait<0>();            // Ga done (mine)
        __syncthreads();
        ACC_INIT(acc2);
        MMA_RANGE(acc2, H2b, H2b + 8192, 256, 0, 4);   // M2h2a: covers A_t skew

        cl_wait();               // A_t: all ranks' h1(t+1) visible

        // Gb: H1buf <- gh1[ns]
        #pragma unroll
        for (int i = 0; i < 4; ++i){
            int idx = tid + i * THREADS;
            int pl = idx >> 9, r = (idx >> 4) & 31, u = idx & 15;
            cpa16(H1b + pl * 8192 + r * 256 + (((u ^ (r & 7)) << 4)),
                  &gh1[ns][(m0 + r) * 256 + pl * 128 + u * 8]);
        }
        cp_commit();

        MMA_RANGE(acc2, H2b, H2b + 8192, 256, 4, 8);   // M2h2b: covers Gb latency

        // acc1 = bias + z1x(t+1)
        #pragma unroll
        for (int g = 0; g < 4; ++g){
            acc1[g][0] = bia[g][0] + zx0[g].x;  acc1[g][1] = bia[g][1] + zx0[g].y;
            acc1[g][2] = bia[g][0] + zx1[g].x;  acc1[g][3] = bia[g][1] + zx1[g].y;
        }

        cp_wait<0>();            // Gb done
        __syncthreads();
        MMA_FUSED(H1b);          // acc1 += h1·U ; acc2 += h1·W

        // ===== E2 + publish h2(t+1) + out =====
        #pragma unroll
        for (int rh = 0; rh < 2; ++rh){
            int j0 = rh * 2, j1 = rh * 2 + 1;
            float cn0 = fsig(acc2[1][j0]) * c2[j0] + fsig(acc2[0][j0]) * ftanh_(acc2[2][j0]);
            float cn1 = fsig(acc2[1][j1]) * c2[j1] + fsig(acc2[0][j1]) * ftanh_(acc2[2][j1]);
            c2[j0] = cn0; c2[j1] = cn1;
            float hv0 = fsig(acc2[3][j0]) * ftanh_(cn0) + h1n[j0];
            float hv1 = fsig(acc2[3][j1]) * ftanh_(cn1) + h1n[j1];
            int r = m0 + R + rh * 8;
            __nv_bfloat162 hh, ll;
            split1(hv0, hh.x, ll.x);
            split1(hv1, hh.y, ll.y);
            *reinterpret_cast<__nv_bfloat162*>(&gh2[ns][r * 256 + gc]) = hh;
            *reinterpret_cast<__nv_bfloat162*>(&gh2[ns][r * 256 + 128 + gc]) = ll;
            float2 ov; ov.x = hv0; ov.y = hv1;
            *reinterpret_cast<float2*>(&out[((size_t)r * TSTEPS + t) * DDIM + gc]) = ov;
        }

        cl_arrive();             // B_t
    }
    cl_wait();

    #undef MMA_FUSED
    #undef MMA_RANGE
    #undef ACC_INIT
}

extern "C" void kernel_launch(void* const* d_in, const int* in_sizes, int n_in,
                              void* d_out, int out_size)
{
    const float* x    = (const float*)d_in[0];
    const float* W    = (const float*)d_in[1];
    const float* U    = (const float*)d_in[2];
    const float* bias = (const float*)d_in[3];
    // d_in[4] = seq_len: reference ignores it
    float* out = (float*)d_out;

    split_w_kernel<<<128, 256>>>(W, U);

    cudaFuncSetAttribute(z1x_kernel,
                         cudaFuncAttributeMaxDynamicSharedMemorySize, SMEM_PRE);
    dim3 gpre(NROWS / 128, 4);
    z1x_kernel<<<gpre, 256, SMEM_PRE>>>(x);

    cudaFuncSetAttribute(lstm_main_kernel,
                         cudaFuncAttributeMaxDynamicSharedMemorySize, SMEM_MAIN);
    lstm_main_kernel<<<128, THREADS, SMEM_MAIN>>>(bias, out);
}

// round 11
// speedup vs baseline: 1.1892x; 1.1892x over previous
#include <cuda_runtime.h>
#include <cuda_bf16.h>
#include <cstdint>

// Problem dims
#define BATCH 1024
#define TSTEPS 200
#define DDIM 128

#define THREADS 256
#define CLUSTER_SIZE 4
#define MT 32                     // batch rows per cluster

// SMEM layout (bytes)
#define SM_BHI 0                  // [128 n][512 B]
#define SM_BLO 65536
#define SM_H1  131072             // 16 KB (hi 8K + lo 8K)
#define SM_H2  147456
#define SM_X   163840             // 2 slots x 16 KB
#define SMEM_MAIN 196608

// device globals (no allocation allowed)
__device__ __nv_bfloat16 gx_hi[(size_t)BATCH*TSTEPS*DDIM];
__device__ __nv_bfloat16 gx_lo[(size_t)BATCH*TSTEPS*DDIM];
__device__ __nv_bfloat16 gh1[2][BATCH*256];  // [slot][row*256 + plane*128 + cell]
__device__ __nv_bfloat16 gh2[2][BATCH*256];

// ---------------- helpers ----------------
__device__ __forceinline__ uint32_t smem_u32(const void* p){
    uint32_t a;
    asm("{ .reg .u64 t; cvta.to.shared.u64 t, %1; cvt.u32.u64 %0, t; }" : "=r"(a) : "l"(p));
    return a;
}
__device__ __forceinline__ uint32_t cl_rank(){
    uint32_t r; asm("mov.u32 %0, %%cluster_ctarank;" : "=r"(r)); return r;
}
__device__ __forceinline__ void cl_arrive(){ asm volatile("barrier.cluster.arrive.aligned;" ::: "memory"); }
__device__ __forceinline__ void cl_wait(){ asm volatile("barrier.cluster.wait.aligned;" ::: "memory"); }
__device__ __forceinline__ void cpa16(uint32_t dst, const void* src){
    asm volatile("cp.async.cg.shared.global [%0], [%1], 16;" :: "r"(dst), "l"(src));
}
__device__ __forceinline__ void cp_commit(){ asm volatile("cp.async.commit_group;" ::: "memory"); }
template<int N> __device__ __forceinline__ void cp_wait(){ asm volatile("cp.async.wait_group %0;" :: "n"(N) : "memory"); }

__device__ __forceinline__ void ldsm4(uint32_t& r0, uint32_t& r1, uint32_t& r2, uint32_t& r3, uint32_t addr){
    asm volatile("ldmatrix.sync.aligned.m8n8.x4.shared.b16 {%0,%1,%2,%3}, [%4];"
                 : "=r"(r0), "=r"(r1), "=r"(r2), "=r"(r3) : "r"(addr));
}
__device__ __forceinline__ void hmma(float* c, const uint32_t* a, uint32_t b0, uint32_t b1){
    asm volatile("mma.sync.aligned.m16n8k16.row.col.f32.bf16.bf16.f32 "
                 "{%0,%1,%2,%3}, {%4,%5,%6,%7}, {%8,%9}, {%0,%1,%2,%3};"
                 : "+f"(c[0]), "+f"(c[1]), "+f"(c[2]), "+f"(c[3])
                 : "r"(a[0]), "r"(a[1]), "r"(a[2]), "r"(a[3]), "r"(b0), "r"(b1));
}
__device__ __forceinline__ float fsig(float x){ return __fdividef(1.f, 1.f + __expf(-x)); }
__device__ __forceinline__ float ftanh_(float x){
    x = fminf(15.f, fmaxf(-15.f, x));
    float e = __expf(2.f * x);
    return __fdividef(e - 1.f, e + 1.f);
}
__device__ __forceinline__ void split1(float v, __nv_bfloat16& hi, __nv_bfloat16& lo){
    hi = __float2bfloat16(v);
    lo = __float2bfloat16(v - __bfloat162float(hi));
}
__device__ __forceinline__ void split4(float4 v, uint2& hi, uint2& lo){
    __nv_bfloat16 hx, hy, hz, hw, lx, ly, lz, lw;
    split1(v.x, hx, lx); split1(v.y, hy, ly); split1(v.z, hz, lz); split1(v.w, hw, lw);
    __nv_bfloat162 h01; h01.x = hx; h01.y = hy;
    __nv_bfloat162 h23; h23.x = hz; h23.y = hw;
    __nv_bfloat162 l01; l01.x = lx; l01.y = ly;
    __nv_bfloat162 l23; l23.x = lz; l23.y = lw;
    hi.x = *reinterpret_cast<uint32_t*>(&h01); hi.y = *reinterpret_cast<uint32_t*>(&h23);
    lo.x = *reinterpret_cast<uint32_t*>(&l01); lo.y = *reinterpret_cast<uint32_t*>(&l23);
}

// -------- pre-kernel: split x into bf16 hi/lo --------
__global__ void __launch_bounds__(256)
split_x_kernel(const float* __restrict__ x)
{
    int i = blockIdx.x * 256 + threadIdx.x;
    float4 v = reinterpret_cast<const float4*>(x)[i];
    uint2 hi, lo; split4(v, hi, lo);
    reinterpret_cast<uint2*>(gx_hi)[i] = hi;
    reinterpret_cast<uint2*>(gx_lo)[i] = lo;
}

extern __shared__ char smem[];

// -------- main persistent kernel: ONE cluster barrier per step --------
__global__ void __launch_bounds__(THREADS, 1) __cluster_dims__(CLUSTER_SIZE, 1, 1)
lstm_main_kernel(const float* __restrict__ W,
                 const float* __restrict__ U,
                 const float* __restrict__ bias,
                 float* __restrict__ out)
{
    const uint32_t sbase = smem_u32(smem);
    const int tid = threadIdx.x;
    const int wid = tid >> 5, lane = tid & 31;
    const uint32_t rank = cl_rank();
    const int m0 = (blockIdx.x >> 2) * MT;

    // ---- B build: n = gate*32 + cell_local, [128 n][512 B] swizzled (one-time)
    #pragma unroll
    for (int i = 0; i < 32; ++i){
        int tsk = tid + i * THREADS;
        int n = tsk >> 6, kq = tsk & 63, k = kq * 4;
        int gate = n >> 5, cell = n & 31;
        int col = gate * 128 + (int)rank * 32 + cell;
        float4 v;
        float* vv = reinterpret_cast<float*>(&v);
        #pragma unroll
        for (int j = 0; j < 4; ++j){
            int kk = k + j;
            vv[j] = (kk < 128) ? W[kk * 512 + col] : U[(kk - 128) * 512 + col];
        }
        uint2 hi, lo; split4(v, hi, lo);
        uint32_t so = n * 512 + ((((kq >> 1) ^ (n & 7)) << 4)) + ((kq & 1) << 3);
        *reinterpret_cast<uint2*>(smem + SM_BHI + so) = hi;
        *reinterpret_cast<uint2*>(smem + SM_BLO + so) = lo;
    }

    // ---- per-warp coordinates (m16 x n32 per warp)
    const int wm = wid & 1, ws = wid >> 1;
    const int a_row = wm * 16 + (lane & 15);
    const uint32_t a_base = a_row * 256;
    const uint32_t a_xor = (a_row & 7) << 4;
    const uint32_t a_lk = (lane >> 4) << 4;
    const int n01 = ws * 8 + (lane & 7) + ((lane >> 4) << 5);
    const int n23 = n01 + 64;
    const uint32_t b01b = n01 * 512, b01x = (n01 & 7) << 4;
    const uint32_t b23b = n23 * 512, b23x = (n23 & 7) << 4;
    const uint32_t b_lk = ((lane >> 3) & 1) << 4;

    const int R = wm * 16 + (lane >> 2);
    const int gc = (int)rank * 32 + ws * 8 + (lane & 3) * 2;

    // ---- prefetch x(0) -> X slot0, x(1) -> X slot1
    #pragma unroll
    for (int slot = 0; slot < 2; ++slot){
        #pragma unroll
        for (int i = 0; i < 4; ++i){
            int idx = tid + i * THREADS;
            int pl = idx >> 9, r = (idx >> 4) & 31, u = idx & 15;
            const __nv_bfloat16* sp = (pl ? gx_lo : gx_hi)
                + ((size_t)(m0 + r) * TSTEPS + slot) * DDIM + u * 8;
            cpa16(sbase + SM_X + slot * 16384 + pl * 8192
                  + r * 256 + (((u ^ (r & 7)) << 4)), sp);
        }
        cp_commit();
    }

    // ---- zero h2(0) own slice (slot 0)
    {
        __nv_bfloat162 z; z.x = __float2bfloat16(0.f); z.y = z.x;
        #pragma unroll
        for (int rh = 0; rh < 2; ++rh){
            int r = m0 + R + rh * 8;
            *reinterpret_cast<__nv_bfloat162*>(&gh2[0][r * 256 + gc]) = z;
            *reinterpret_cast<__nv_bfloat162*>(&gh2[0][r * 256 + 128 + gc]) = z;
        }
    }

    float bia[4][2];
    #pragma unroll
    for (int g = 0; g < 4; ++g){
        bia[g][0] = bias[g * 128 + gc];
        bia[g][1] = bias[g * 128 + gc + 1];
    }

    float c1[4], c2[4], h1n[4];
    #pragma unroll
    for (int j = 0; j < 4; ++j){ c1[j] = 0.f; c2[j] = 0.f; }

    float acc1[4][4], acc2[4][4];

    #define ACC_INIT(A)                                         \
        _Pragma("unroll")                                       \
        for (int g = 0; g < 4; ++g){                            \
            A[g][0] = bia[g][0]; A[g][1] = bia[g][1];           \
            A[g][2] = bia[g][0]; A[g][3] = bia[g][1];           \
        }

    #define MMA_RANGE(A, AHI, ALO, BOFS, K0, K1)                                       \
    {                                                                                  \
        _Pragma("unroll")                                                              \
        for (int ks = (K0); ks < (K1); ++ks){                                          \
            uint32_t kbA = (uint32_t)(ks * 32) + a_lk;                                 \
            uint32_t kbB = (uint32_t)(ks * 32) + (uint32_t)(BOFS) + b_lk;              \
            uint32_t ahi[4], alo[4], bh[8], bl[8];                                     \
            ldsm4(ahi[0], ahi[1], ahi[2], ahi[3], (AHI) + a_base + (kbA ^ a_xor));     \
            ldsm4(alo[0], alo[1], alo[2], alo[3], (ALO) + a_base + (kbA ^ a_xor));     \
            ldsm4(bh[0], bh[1], bh[2], bh[3], sbase + SM_BHI + b01b + (kbB ^ b01x));   \
            ldsm4(bh[4], bh[5], bh[6], bh[7], sbase + SM_BHI + b23b + (kbB ^ b23x));   \
            ldsm4(bl[0], bl[1], bl[2], bl[3], sbase + SM_BLO + b01b + (kbB ^ b01x));   \
            ldsm4(bl[4], bl[5], bl[6], bl[7], sbase + SM_BLO + b23b + (kbB ^ b23x));   \
            _Pragma("unroll")                                                          \
            for (int g = 0; g < 4; ++g){                                               \
                hmma(A[g], ahi, bh[g*2], bh[g*2+1]);                                   \
                hmma(A[g], ahi, bl[g*2], bl[g*2+1]);                                   \
                hmma(A[g], alo, bh[g*2], bh[g*2+1]);                                   \
            }                                                                          \
        }                                                                              \
    }

    // fused: A = h1(t+1); U half -> acc1, W half -> acc2 (A-frags loaded once)
    #define MMA_FUSED(H1B)                                                             \
    {                                                                                  \
        _Pragma("unroll")                                                              \
        for (int ks = 0; ks < 8; ++ks){                                                \
            uint32_t kbA = (uint32_t)(ks * 32) + a_lk;                                 \
            uint32_t kbU = (uint32_t)(ks * 32) + 256u + b_lk;                          \
            uint32_t kbW = (uint32_t)(ks * 32) + b_lk;                                 \
            uint32_t ahi[4], alo[4], bhU[8], blU[8], bhW[8], blW[8];                   \
            ldsm4(ahi[0], ahi[1], ahi[2], ahi[3], (H1B) + a_base + (kbA ^ a_xor));     \
            ldsm4(alo[0], alo[1], alo[2], alo[3], (H1B) + 8192 + a_base + (kbA ^ a_xor)); \
            ldsm4(bhU[0], bhU[1], bhU[2], bhU[3], sbase + SM_BHI + b01b + (kbU ^ b01x)); \
            ldsm4(bhU[4], bhU[5], bhU[6], bhU[7], sbase + SM_BHI + b23b + (kbU ^ b23x)); \
            ldsm4(blU[0], blU[1], blU[2], blU[3], sbase + SM_BLO + b01b + (kbU ^ b01x)); \
            ldsm4(blU[4], blU[5], blU[6], blU[7], sbase + SM_BLO + b23b + (kbU ^ b23x)); \
            ldsm4(bhW[0], bhW[1], bhW[2], bhW[3], sbase + SM_BHI + b01b + (kbW ^ b01x)); \
            ldsm4(bhW[4], bhW[5], bhW[6], bhW[7], sbase + SM_BHI + b23b + (kbW ^ b23x)); \
            ldsm4(blW[0], blW[1], blW[2], blW[3], sbase + SM_BLO + b01b + (kbW ^ b01x)); \
            ldsm4(blW[4], blW[5], blW[6], blW[7], sbase + SM_BLO + b23b + (kbW ^ b23x)); \
            _Pragma("unroll")                                                          \
            for (int g = 0; g < 4; ++g){                                               \
                hmma(acc1[g], ahi, bhU[g*2], bhU[g*2+1]);                              \
                hmma(acc1[g], ahi, blU[g*2], blU[g*2+1]);                              \
                hmma(acc1[g], alo, bhU[g*2], bhU[g*2+1]);                              \
                hmma(acc2[g], ahi, bhW[g*2], bhW[g*2+1]);                              \
                hmma(acc2[g], ahi, blW[g*2], blW[g*2+1]);                              \
                hmma(acc2[g], alo, bhW[g*2], bhW[g*2+1]);                              \
            }                                                                          \
        }                                                                              \
    }

    const uint32_t H1b = sbase + SM_H1, H2b = sbase + SM_H2;

    // ---- prologue: acc1 = bias + x(0)·W  -> E1 -> h1(1) published to gh1[1]
    cp_wait<0>();
    __syncthreads();
    ACC_INIT(acc1);
    MMA_RANGE(acc1, sbase + SM_X, sbase + SM_X + 8192, 0, 0, 8);
    #pragma unroll
    for (int j = 0; j < 4; ++j){
        float cn = fsig(acc1[1][j]) * c1[j] + fsig(acc1[0][j]) * ftanh_(acc1[2][j]);
        c1[j] = cn;
        h1n[j] = fsig(acc1[3][j]) * ftanh_(cn);
    }
    #pragma unroll
    for (int rh = 0; rh < 2; ++rh){
        int r = m0 + R + rh * 8;
        __nv_bfloat162 hh, ll;
        split1(h1n[rh * 2 + 0], hh.x, ll.x);
        split1(h1n[rh * 2 + 1], hh.y, ll.y);
        *reinterpret_cast<__nv_bfloat162*>(&gh1[1][r * 256 + gc]) = hh;
        *reinterpret_cast<__nv_bfloat162*>(&gh1[1][r * 256 + 128 + gc]) = ll;
    }
    cl_arrive();     // B_{-1}: h1(1), h2(0) published

    for (int t = 0; t < TSTEPS; ++t){
        const int s = t & 1, ns = s ^ 1;
        const uint32_t Xrd = sbase + SM_X + ns * 16384;   // x(t+1)
        const uint32_t Xwr = sbase + SM_X + s * 16384;    // refill x(t+2)

        cl_wait();   // B_{t-1}: h1(t+1) [gh1[ns]] and h2(t) [gh2[s]] visible

        // Ga (group 0): H2buf <- gh2[s]
        #pragma unroll
        for (int i = 0; i < 4; ++i){
            int idx = tid + i * THREADS;
            int pl = idx >> 9, r = (idx >> 4) & 31, u = idx & 15;
            cpa16(H2b + pl * 8192 + r * 256 + (((u ^ (r & 7)) << 4)),
                  &gh2[s][(m0 + r) * 256 + pl * 128 + u * 8]);
        }
        cp_commit();
        // Gb (group 1): H1buf <- gh1[ns]; X refill x(t+2)
        #pragma unroll
        for (int i = 0; i < 4; ++i){
            int idx = tid + i * THREADS;
            int pl = idx >> 9, r = (idx >> 4) & 31, u = idx & 15;
            cpa16(H1b + pl * 8192 + r * 256 + (((u ^ (r & 7)) << 4)),
                  &gh1[ns][(m0 + r) * 256 + pl * 128 + u * 8]);
        }
        if (t + 2 < TSTEPS){
            #pragma unroll
            for (int i = 0; i < 4; ++i){
                int idx = tid + i * THREADS;
                int pl = idx >> 9, r = (idx >> 4) & 31, u = idx & 15;
                const __nv_bfloat16* sp = (pl ? gx_lo : gx_hi)
                    + ((size_t)(m0 + r) * TSTEPS + (t + 2)) * DDIM + u * 8;
                cpa16(Xwr + pl * 8192 + r * 256 + (((u ^ (r & 7)) << 4)), sp);
            }
        }
        cp_commit();

        // M1x: acc1 = bias + x(t+1)·W   (covers readback latencies)
        ACC_INIT(acc1);
        if (t + 1 < TSTEPS)
            MMA_RANGE(acc1, Xrd, Xrd + 8192, 0, 0, 8);

        cp_wait<1>();    // Ga done
        __syncthreads();
        // M2h2: acc2 = bias + h2(t)·U
        ACC_INIT(acc2);
        MMA_RANGE(acc2, H2b, H2b + 8192, 256, 0, 8);

        cp_wait<0>();    // Gb done
        __syncthreads();
        MMA_FUSED(H1b);  // acc1 += h1(t+1)·U ; acc2 += h1(t+1)·W

        // ===== E2 (layer 2, step t) then E1 (layer 1, h1(t+2)) =====
        float hv[4];
        #pragma unroll
        for (int j = 0; j < 4; ++j){
            float cn = fsig(acc2[1][j]) * c2[j] + fsig(acc2[0][j]) * ftanh_(acc2[2][j]);
            c2[j] = cn;
            hv[j] = fsig(acc2[3][j]) * ftanh_(cn) + h1n[j];   // residual h1(t+1)
        }
        #pragma unroll
        for (int j = 0; j < 4; ++j){
            float cn = fsig(acc1[1][j]) * c1[j] + fsig(acc1[0][j]) * ftanh_(acc1[2][j]);
            c1[j] = cn;
            h1n[j] = fsig(acc1[3][j]) * ftanh_(cn);           // h1(t+2)
        }

        // publish h2(t+1) -> gh2[ns], h1(t+2) -> gh1[s]; out(t)
        #pragma unroll
        for (int rh = 0; rh < 2; ++rh){
            int r = m0 + R + rh * 8;
            __nv_bfloat162 hh, ll;
            split1(hv[rh * 2 + 0], hh.x, ll.x);
            split1(hv[rh * 2 + 1], hh.y, ll.y);
            *reinterpret_cast<__nv_bfloat162*>(&gh2[ns][r * 256 + gc]) = hh;
            *reinterpret_cast<__nv_bfloat162*>(&gh2[ns][r * 256 + 128 + gc]) = ll;
            __nv_bfloat162 h1h, h1l;
            split1(h1n[rh * 2 + 0], h1h.x, h1l.x);
            split1(h1n[rh * 2 + 1], h1h.y, h1l.y);
            *reinterpret_cast<__nv_bfloat162*>(&gh1[s][r * 256 + gc]) = h1h;
            *reinterpret_cast<__nv_bfloat162*>(&gh1[s][r * 256 + 128 + gc]) = h1l;
            float2 ov; ov.x = hv[rh * 2 + 0]; ov.y = hv[rh * 2 + 1];
            *reinterpret_cast<float2*>(&out[((size_t)r * TSTEPS + t) * DDIM + gc]) = ov;
        }

        cl_arrive();     // B_t
    }
    cl_wait();           // consume final arrive

    #undef MMA_FUSED
    #undef MMA_RANGE
    #undef ACC_INIT
}

extern "C" void kernel_launch(void* const* d_in, const int* in_sizes, int n_in,
                              void* d_out, int out_size)
{
    const float* x    = (const float*)d_in[0];
    const float* W    = (const float*)d_in[1];
    const float* U    = (const float*)d_in[2];
    const float* bias = (const float*)d_in[3];
    // d_in[4] = seq_len: reference ignores it
    float* out = (float*)d_out;

    split_x_kernel<<<(BATCH * TSTEPS * DDIM / 4) / 256, 256>>>(x);

    cudaFuncSetAttribute(lstm_main_kernel,
                         cudaFuncAttributeMaxDynamicSharedMemorySize, SMEM_MAIN);
    lstm_main_kernel<<<128, THREADS, SMEM_MAIN>>>(W, U, bias, out);
}

// round 13
// speedup vs baseline: 1.2858x; 1.0812x over previous
#include <cuda_runtime.h>
#include <cuda_bf16.h>
#include <cstdint>

// Problem dims
#define BATCH 1024
#define TSTEPS 200
#define DDIM 128

#define THREADS 256
#define CLUSTER_SIZE 4
#define MT 32                     // batch rows per cluster

// SMEM layout (bytes)
#define SM_BHI 0                  // [128 n][512 B]
#define SM_BLO 65536
#define SM_H1  131072             // 16 KB (hi 8K + lo 8K)
#define SM_H2  147456
#define SM_X   163840             // 2 slots x 16 KB
#define SMEM_MAIN 196608

// device globals (no allocation allowed)
__device__ __nv_bfloat16 gx_hi[(size_t)BATCH*TSTEPS*DDIM];
__device__ __nv_bfloat16 gx_lo[(size_t)BATCH*TSTEPS*DDIM];
__device__ __nv_bfloat16 gh1[2][BATCH*256];  // [slot][row*256 + plane*128 + cell]
__device__ __nv_bfloat16 gh2[2][BATCH*256];

// ---------------- helpers ----------------
__device__ __forceinline__ uint32_t smem_u32(const void* p){
    uint32_t a;
    asm("{ .reg .u64 t; cvta.to.shared.u64 t, %1; cvt.u32.u64 %0, t; }" : "=r"(a) : "l"(p));
    return a;
}
__device__ __forceinline__ uint32_t cl_rank(){
    uint32_t r; asm("mov.u32 %0, %%cluster_ctarank;" : "=r"(r)); return r;
}
__device__ __forceinline__ void cl_arrive(){ asm volatile("barrier.cluster.arrive.aligned;" ::: "memory"); }
__device__ __forceinline__ void cl_wait(){ asm volatile("barrier.cluster.wait.aligned;" ::: "memory"); }
__device__ __forceinline__ void barn(int id){ asm volatile("bar.sync %0, 128;" :: "r"(id) : "memory"); }
__device__ __forceinline__ void cpa16(uint32_t dst, const void* src){
    asm volatile("cp.async.cg.shared.global [%0], [%1], 16;" :: "r"(dst), "l"(src));
}
__device__ __forceinline__ void cp_commit(){ asm volatile("cp.async.commit_group;" ::: "memory"); }
template<int N> __device__ __forceinline__ void cp_wait(){ asm volatile("cp.async.wait_group %0;" :: "n"(N) : "memory"); }

__device__ __forceinline__ void ldsm4(uint32_t& r0, uint32_t& r1, uint32_t& r2, uint32_t& r3, uint32_t addr){
    asm volatile("ldmatrix.sync.aligned.m8n8.x4.shared.b16 {%0,%1,%2,%3}, [%4];"
                 : "=r"(r0), "=r"(r1), "=r"(r2), "=r"(r3) : "r"(addr));
}
__device__ __forceinline__ void hmma(float* c, const uint32_t* a, uint32_t b0, uint32_t b1){
    asm volatile("mma.sync.aligned.m16n8k16.row.col.f32.bf16.bf16.f32 "
                 "{%0,%1,%2,%3}, {%4,%5,%6,%7}, {%8,%9}, {%0,%1,%2,%3};"
                 : "+f"(c[0]), "+f"(c[1]), "+f"(c[2]), "+f"(c[3])
                 : "r"(a[0]), "r"(a[1]), "r"(a[2]), "r"(a[3]), "r"(b0), "r"(b1));
}
__device__ __forceinline__ float fsig(float x){ return __fdividef(1.f, 1.f + __expf(-x)); }
__device__ __forceinline__ float ftanh_(float x){
    x = fminf(15.f, fmaxf(-15.f, x));
    float e = __expf(2.f * x);
    return __fdividef(e - 1.f, e + 1.f);
}
__device__ __forceinline__ void split1(float v, __nv_bfloat16& hi, __nv_bfloat16& lo){
    hi = __float2bfloat16(v);
    lo = __float2bfloat16(v - __bfloat162float(hi));
}
__device__ __forceinline__ void split4(float4 v, uint2& hi, uint2& lo){
    __nv_bfloat16 hx, hy, hz, hw, lx, ly, lz, lw;
    split1(v.x, hx, lx); split1(v.y, hy, ly); split1(v.z, hz, lz); split1(v.w, hw, lw);
    __nv_bfloat162 h01; h01.x = hx; h01.y = hy;
    __nv_bfloat162 h23; h23.x = hz; h23.y = hw;
    __nv_bfloat162 l01; l01.x = lx; l01.y = ly;
    __nv_bfloat162 l23; l23.x = lz; l23.y = lw;
    hi.x = *reinterpret_cast<uint32_t*>(&h01); hi.y = *reinterpret_cast<uint32_t*>(&h23);
    lo.x = *reinterpret_cast<uint32_t*>(&l01); lo.y = *reinterpret_cast<uint32_t*>(&l23);
}

// -------- pre-kernel: split x into bf16 hi/lo --------
__global__ void __launch_bounds__(256)
split_x_kernel(const float* __restrict__ x)
{
    int i = blockIdx.x * 256 + threadIdx.x;
    float4 v = reinterpret_cast<const float4*>(x)[i];
    uint2 hi, lo; split4(v, hi, lo);
    reinterpret_cast<uint2*>(gx_hi)[i] = hi;
    reinterpret_cast<uint2*>(gx_lo)[i] = lo;
}

extern __shared__ char smem[];

// -------- main persistent kernel: layer-per-warp, one cluster barrier/step --------
__global__ void __launch_bounds__(THREADS, 1) __cluster_dims__(CLUSTER_SIZE, 1, 1)
lstm_main_kernel(const float* __restrict__ W,
                 const float* __restrict__ U,
                 const float* __restrict__ bias,
                 float* __restrict__ out)
{
    const uint32_t sbase = smem_u32(smem);
    const int tid = threadIdx.x;
    const int wid = tid >> 5, lane = tid & 31;
    const uint32_t rank = cl_rank();
    const int m0 = (blockIdx.x >> 2) * MT;
    const int layer = wid >> 2;          // 0: layer1 warps, 1: layer2 warps
    const int ws = wid & 3;              // n32 cell-slice
    const int lt = tid & 127;            // index within layer group

    // ---- B build: n = gate*32 + cell_local, [128 n][512 B] swizzled (one-time)
    #pragma unroll
    for (int i = 0; i < 32; ++i){
        int tsk = tid + i * THREADS;
        int n = tsk >> 6, kq = tsk & 63, k = kq * 4;
        int gate = n >> 5, cell = n & 31;
        int col = gate * 128 + (int)rank * 32 + cell;
        float4 v;
        float* vv = reinterpret_cast<float*>(&v);
        #pragma unroll
        for (int j = 0; j < 4; ++j){
            int kk = k + j;
            vv[j] = (kk < 128) ? W[kk * 512 + col] : U[(kk - 128) * 512 + col];
        }
        uint2 hi, lo; split4(v, hi, lo);
        uint32_t so = n * 512 + ((((kq >> 1) ^ (n & 7)) << 4)) + ((kq & 1) << 3);
        *reinterpret_cast<uint2*>(smem + SM_BHI + so) = hi;
        *reinterpret_cast<uint2*>(smem + SM_BLO + so) = lo;
    }

    // ---- prefetch x(0) -> X slot0, x(1) -> X slot1 (all threads)
    #pragma unroll
    for (int slot = 0; slot < 2; ++slot){
        #pragma unroll
        for (int i = 0; i < 4; ++i){
            int idx = tid + i * THREADS;
            int pl = idx >> 9, r = (idx >> 4) & 31, u = idx & 15;
            const __nv_bfloat16* sp = (pl ? gx_lo : gx_hi)
                + ((size_t)(m0 + r) * TSTEPS + slot) * DDIM + u * 8;
            cpa16(sbase + SM_X + slot * 16384 + pl * 8192
                  + r * 256 + (((u ^ (r & 7)) << 4)), sp);
        }
        cp_commit();
    }

    // ---- per-warp coordinates: m32 x n32 tile
    const int a_row0 = lane & 15;
    const int a_row1 = a_row0 + 16;
    const uint32_t a0b = a_row0 * 256, a0x = (a_row0 & 7) << 4;
    const uint32_t a1b = a_row1 * 256, a1x = (a_row1 & 7) << 4;
    const uint32_t a_lk = (lane >> 4) << 4;
    const int n01 = ws * 8 + (lane & 7) + ((lane >> 4) << 5);
    const int n23 = n01 + 64;
    const uint32_t b01b = n01 * 512, b01x = (n01 & 7) << 4;
    const uint32_t b23b = n23 * 512, b23x = (n23 & 7) << 4;
    const uint32_t b_lk = ((lane >> 3) & 1) << 4;

    const int R0 = lane >> 2;                                 // local rows R0 + {0,8,16,24}
    const int gc = (int)rank * 32 + ws * 8 + (lane & 3) * 2;  // global cells gc, gc+1

    // ---- zero h2(0) own slice (layer2 warps)
    if (layer == 1){
        __nv_bfloat162 z; z.x = __float2bfloat16(0.f); z.y = z.x;
        #pragma unroll
        for (int rr = 0; rr < 4; ++rr){
            int r = m0 + R0 + rr * 8;
            *reinterpret_cast<__nv_bfloat162*>(&gh2[0][r * 256 + gc]) = z;
            *reinterpret_cast<__nv_bfloat162*>(&gh2[0][r * 256 + 128 + gc]) = z;
        }
    }

    float bia[4][2];
    #pragma unroll
    for (int g = 0; g < 4; ++g){
        bia[g][0] = bias[g * 128 + gc];
        bia[g][1] = bias[g * 128 + gc + 1];
    }

    float cst[8];                 // c1 (layer-1 warps) or c2 (layer-2 warps)
    #pragma unroll
    for (int j = 0; j < 8; ++j) cst[j] = 0.f;

    float acc[2][4][4];

    #define ACC_INIT()                                          \
        _Pragma("unroll")                                       \
        for (int mf = 0; mf < 2; ++mf)                          \
            _Pragma("unroll")                                   \
            for (int g = 0; g < 4; ++g){                        \
                acc[mf][g][0] = bia[g][0]; acc[mf][g][1] = bia[g][1]; \
                acc[mf][g][2] = bia[g][0]; acc[mf][g][3] = bia[g][1]; \
            }

    // full K=128 GEMM onto acc: A m32 from (AHI, ALO), B rows at +BOFS bytes
    #define MMA8(AHI, ALO, BOFS)                                                       \
    {                                                                                  \
        _Pragma("unroll")                                                              \
        for (int ks = 0; ks < 8; ++ks){                                                \
            uint32_t kbA = (uint32_t)(ks * 32) + a_lk;                                 \
            uint32_t kbB = (uint32_t)(ks * 32) + (uint32_t)(BOFS) + b_lk;              \
            uint32_t ah0[4], al0[4], ah1[4], al1[4], bh[8], bl[8];                     \
            ldsm4(ah0[0], ah0[1], ah0[2], ah0[3], (AHI) + a0b + (kbA ^ a0x));          \
            ldsm4(al0[0], al0[1], al0[2], al0[3], (ALO) + a0b + (kbA ^ a0x));          \
            ldsm4(ah1[0], ah1[1], ah1[2], ah1[3], (AHI) + a1b + (kbA ^ a1x));          \
            ldsm4(al1[0], al1[1], al1[2], al1[3], (ALO) + a1b + (kbA ^ a1x));          \
            ldsm4(bh[0], bh[1], bh[2], bh[3], sbase + SM_BHI + b01b + (kbB ^ b01x));   \
            ldsm4(bh[4], bh[5], bh[6], bh[7], sbase + SM_BHI + b23b + (kbB ^ b23x));   \
            ldsm4(bl[0], bl[1], bl[2], bl[3], sbase + SM_BLO + b01b + (kbB ^ b01x));   \
            ldsm4(bl[4], bl[5], bl[6], bl[7], sbase + SM_BLO + b23b + (kbB ^ b23x));   \
            _Pragma("unroll")                                                          \
            for (int g = 0; g < 4; ++g){                                               \
                hmma(acc[0][g], ah0, bh[g*2], bh[g*2+1]);                              \
                hmma(acc[0][g], ah0, bl[g*2], bl[g*2+1]);                              \
                hmma(acc[0][g], al0, bh[g*2], bh[g*2+1]);                              \
                hmma(acc[1][g], ah1, bh[g*2], bh[g*2+1]);                              \
                hmma(acc[1][g], ah1, bl[g*2], bl[g*2+1]);                              \
                hmma(acc[1][g], al1, bh[g*2], bh[g*2+1]);                              \
            }                                                                          \
        }                                                                              \
    }

    const uint32_t H1b = sbase + SM_H1, H2b = sbase + SM_H2;

    // ---- prologue: layer1 computes h1(1) = E1(bias + x(0)·W); publish to gh1[1]
    cp_wait<0>();
    __syncthreads();
    if (layer == 0){
        ACC_INIT();
        MMA8(sbase + SM_X, sbase + SM_X + 8192, 0);
        float hv[8];
        #pragma unroll
        for (int mf = 0; mf < 2; ++mf)
            #pragma unroll
            for (int v = 0; v < 4; ++v){
                int j = mf * 4 + v;
                float cn = fsig(acc[mf][1][v]) * cst[j]
                         + fsig(acc[mf][0][v]) * ftanh_(acc[mf][2][v]);
                cst[j] = cn;
                hv[j] = fsig(acc[mf][3][v]) * ftanh_(cn);
            }
        #pragma unroll
        for (int rr = 0; rr < 4; ++rr){
            int r = m0 + R0 + rr * 8;
            int j0 = (rr >> 1) * 4 + (rr & 1) * 2;
            __nv_bfloat162 hh, ll;
            split1(hv[j0], hh.x, ll.x);
            split1(hv[j0 + 1], hh.y, ll.y);
            *reinterpret_cast<__nv_bfloat162*>(&gh1[1][r * 256 + gc]) = hh;
            *reinterpret_cast<__nv_bfloat162*>(&gh1[1][r * 256 + 128 + gc]) = ll;
        }
    }
    cl_arrive();     // B_{-1}: h1(1), h2(0) published

    for (int t = 0; t < TSTEPS; ++t){
        const int s = t & 1, ns = s ^ 1;
        const uint32_t Xrd = sbase + SM_X + ns * 16384;   // x(t+1)
        const uint32_t Xwr = sbase + SM_X + s * 16384;    // refill x(t+2)

        cl_wait();   // B_{t-1}: h1(t+1) [gh1[ns]] and h2(t) [gh2[s]] visible

        if (layer == 1){
            // Ga (L2-only): H2b <- gh2[s]
            #pragma unroll
            for (int i = 0; i < 8; ++i){
                int idx = lt + i * 128;
                int pl = idx >> 9, r = (idx >> 4) & 31, u = idx & 15;
                cpa16(H2b + pl * 8192 + r * 256 + (((u ^ (r & 7)) << 4)),
                      &gh2[s][(m0 + r) * 256 + pl * 128 + u * 8]);
            }
            cp_commit();
        } else {
            // X refill (L1-only): x(t+2)
            if (t + 2 < TSTEPS){
                #pragma unroll
                for (int i = 0; i < 8; ++i){
                    int idx = lt + i * 128;
                    int pl = idx >> 9, r = (idx >> 4) & 31, u = idx & 15;
                    const __nv_bfloat16* sp = (pl ? gx_lo : gx_hi)
                        + ((size_t)(m0 + r) * TSTEPS + (t + 2)) * DDIM + u * 8;
                    cpa16(Xwr + pl * 8192 + r * 256 + (((u ^ (r & 7)) << 4)), sp);
                }
            }
            cp_commit();
        }
        // Gb (all threads): H1b <- gh1[ns]
        #pragma unroll
        for (int i = 0; i < 4; ++i){
            int idx = tid + i * THREADS;
            int pl = idx >> 9, r = (idx >> 4) & 31, u = idx & 15;
            cpa16(H1b + pl * 8192 + r * 256 + (((u ^ (r & 7)) << 4)),
                  &gh1[ns][(m0 + r) * 256 + pl * 128 + u * 8]);
        }
        cp_commit();

        // ===== phase A =====
        ACC_INIT();
        if (layer == 0){
            // z1(t+1) partial: x(t+1)·W  (X resident since prev step)
            if (t + 1 < TSTEPS){
                MMA8(Xrd, Xrd + 8192, 0);
            }
        } else {
            cp_wait<1>();        // Ga done (own groups: Ga, Gb)
            barn(1);             // L2 warps rendezvous: H2b CTA-visible
            // z2(t) partial: h2(t)·U
            MMA8(H2b, H2b + 8192, 256);
        }

        cp_wait<0>();            // all own groups done (incl. Gb)
        __syncthreads();         // H1b visible to everyone

        // ===== phase B: h1(t+1) GEMMs =====
        if (layer == 0){
            MMA8(H1b, H1b + 8192, 256);   // z1 += h1(t+1)·U
        } else {
            MMA8(H1b, H1b + 8192, 0);     // z2 += h1(t+1)·W
        }

        // ===== epilogues (parallel across layer groups) =====
        if (layer == 0){
            float hv[8];
            #pragma unroll
            for (int mf = 0; mf < 2; ++mf)
                #pragma unroll
                for (int v = 0; v < 4; ++v){
                    int j = mf * 4 + v;
                    float cn = fsig(acc[mf][1][v]) * cst[j]
                             + fsig(acc[mf][0][v]) * ftanh_(acc[mf][2][v]);
                    cst[j] = cn;
                    hv[j] = fsig(acc[mf][3][v]) * ftanh_(cn);   // h1(t+2)
                }
            #pragma unroll
            for (int rr = 0; rr < 4; ++rr){
                int r = m0 + R0 + rr * 8;
                int j0 = (rr >> 1) * 4 + (rr & 1) * 2;
                __nv_bfloat162 hh, ll;
                split1(hv[j0], hh.x, ll.x);
                split1(hv[j0 + 1], hh.y, ll.y);
                *reinterpret_cast<__nv_bfloat162*>(&gh1[s][r * 256 + gc]) = hh;
                *reinterpret_cast<__nv_bfloat162*>(&gh1[s][r * 256 + 128 + gc]) = ll;
            }
        } else {
            // residual h1(t+1) from H1b (hi+lo reconstruct)
            float res[8];
            #pragma unroll
            for (int rr = 0; rr < 4; ++rr){
                int rloc = R0 + rr * 8;
                uint32_t ho = (uint32_t)(rloc * 256
                            + ((((uint32_t)(gc >> 3) ^ (uint32_t)(rloc & 7))) << 4)
                            + ((2 * gc) & 15));
                __nv_bfloat162 hh = *reinterpret_cast<const __nv_bfloat162*>(smem + SM_H1 + ho);
                __nv_bfloat162 ll = *reinterpret_cast<const __nv_bfloat162*>(smem + SM_H1 + 8192 + ho);
                res[rr * 2 + 0] = __bfloat162float(hh.x) + __bfloat162float(ll.x);
                res[rr * 2 + 1] = __bfloat162float(hh.y) + __bfloat162float(ll.y);
            }
            float hv[8];
            #pragma unroll
            for (int mf = 0; mf < 2; ++mf)
                #pragma unroll
                for (int v = 0; v < 4; ++v){
                    int j = mf * 4 + v;
                    float cn = fsig(acc[mf][1][v]) * cst[j]
                             + fsig(acc[mf][0][v]) * ftanh_(acc[mf][2][v]);
                    cst[j] = cn;
                    hv[j] = fsig(acc[mf][3][v]) * ftanh_(cn);
                }
            #pragma unroll
            for (int rr = 0; rr < 4; ++rr){
                int rloc = R0 + rr * 8;
                int r = m0 + rloc;
                int j0 = (rr >> 1) * 4 + (rr & 1) * 2;
                float h0 = hv[j0] + res[rr * 2 + 0];      // + residual h1(t+1)
                float h1v = hv[j0 + 1] + res[rr * 2 + 1];
                __nv_bfloat162 hh, ll;
                split1(h0, hh.x, ll.x);
                split1(h1v, hh.y, ll.y);
                *reinterpret_cast<__nv_bfloat162*>(&gh2[ns][r * 256 + gc]) = hh;
                *reinterpret_cast<__nv_bfloat162*>(&gh2[ns][r * 256 + 128 + gc]) = ll;
                float2 ov; ov.x = h0; ov.y = h1v;
                *reinterpret_cast<float2*>(&out[((size_t)r * TSTEPS + t) * DDIM + gc]) = ov;
            }
        }

        cl_arrive();     // B_t: h1(t+2) + h2(t+1) published
    }
    cl_wait();           // consume final arrive

    #undef MMA8
    #undef ACC_INIT
}

extern "C" void kernel_launch(void* const* d_in, const int* in_sizes, int n_in,
                              void* d_out, int out_size)
{
    const float* x    = (const float*)d_in[0];
    const float* W    = (const float*)d_in[1];
    const float* U    = (const float*)d_in[2];
    const float* bias = (const float*)d_in[3];
    // d_in[4] = seq_len: reference ignores it
    float* out = (float*)d_out;

    split_x_kernel<<<(BATCH * TSTEPS * DDIM / 4) / 256, 256>>>(x);

    cudaFuncSetAttribute(lstm_main_kernel,
                         cudaFuncAttributeMaxDynamicSharedMemorySize, SMEM_MAIN);
    lstm_main_kernel<<<128, THREADS, SMEM_MAIN>>>(W, U, bias, out);
}

// round 14
// speedup vs baseline: 1.3020x; 1.0126x over previous
#include <cuda_runtime.h>
#include <cuda_bf16.h>
#include <cstdint>

// Problem dims
#define BATCH 1024
#define TSTEPS 200
#define DDIM 128

#define THREADS 256
#define CLUSTER_SIZE 4
#define MT 32                     // batch rows per cluster

// SMEM layout (bytes)
#define SM_BHI 0                  // [128 n][512 B]
#define SM_BLO 65536
#define SM_H1A 131072             // L1's h1(t+1) copy: 16 KB (hi 8K + lo 8K)
#define SM_H1C 147456             // L2's h1(t+1) copy: 16 KB
#define SM_H2  163840             // 16 KB
#define SM_X   180224             // 2 slots x 16 KB
#define SMEM_MAIN 212992

// device globals (no allocation allowed)
__device__ __nv_bfloat16 gx_hi[(size_t)BATCH*TSTEPS*DDIM];
__device__ __nv_bfloat16 gx_lo[(size_t)BATCH*TSTEPS*DDIM];
__device__ __nv_bfloat16 gh1[2][BATCH*256];  // [slot][row*256 + plane*128 + cell]
__device__ __nv_bfloat16 gh2[2][BATCH*256];

// ---------------- helpers ----------------
__device__ __forceinline__ uint32_t smem_u32(const void* p){
    uint32_t a;
    asm("{ .reg .u64 t; cvta.to.shared.u64 t, %1; cvt.u32.u64 %0, t; }" : "=r"(a) : "l"(p));
    return a;
}
__device__ __forceinline__ uint32_t cl_rank(){
    uint32_t r; asm("mov.u32 %0, %%cluster_ctarank;" : "=r"(r)); return r;
}
__device__ __forceinline__ void cl_arrive(){ asm volatile("barrier.cluster.arrive.aligned;" ::: "memory"); }
__device__ __forceinline__ void cl_wait(){ asm volatile("barrier.cluster.wait.aligned;" ::: "memory"); }
__device__ __forceinline__ void barn(int id){ asm volatile("bar.sync %0, 128;" :: "r"(id) : "memory"); }
__device__ __forceinline__ void cpa16(uint32_t dst, const void* src){
    asm volatile("cp.async.cg.shared.global [%0], [%1], 16;" :: "r"(dst), "l"(src));
}
__device__ __forceinline__ void cp_commit(){ asm volatile("cp.async.commit_group;" ::: "memory"); }
template<int N> __device__ __forceinline__ void cp_wait(){ asm volatile("cp.async.wait_group %0;" :: "n"(N) : "memory"); }

__device__ __forceinline__ void ldsm4(uint32_t& r0, uint32_t& r1, uint32_t& r2, uint32_t& r3, uint32_t addr){
    asm volatile("ldmatrix.sync.aligned.m8n8.x4.shared.b16 {%0,%1,%2,%3}, [%4];"
                 : "=r"(r0), "=r"(r1), "=r"(r2), "=r"(r3) : "r"(addr));
}
__device__ __forceinline__ void hmma(float* c, const uint32_t* a, uint32_t b0, uint32_t b1){
    asm volatile("mma.sync.aligned.m16n8k16.row.col.f32.bf16.bf16.f32 "
                 "{%0,%1,%2,%3}, {%4,%5,%6,%7}, {%8,%9}, {%0,%1,%2,%3};"
                 : "+f"(c[0]), "+f"(c[1]), "+f"(c[2]), "+f"(c[3])
                 : "r"(a[0]), "r"(a[1]), "r"(a[2]), "r"(a[3]), "r"(b0), "r"(b1));
}
__device__ __forceinline__ float fsig(float x){ return __fdividef(1.f, 1.f + __expf(-x)); }
__device__ __forceinline__ float ftanh_(float x){
    x = fminf(15.f, fmaxf(-15.f, x));
    float e = __expf(2.f * x);
    return __fdividef(e - 1.f, e + 1.f);
}
__device__ __forceinline__ void split1(float v, __nv_bfloat16& hi, __nv_bfloat16& lo){
    hi = __float2bfloat16(v);
    lo = __float2bfloat16(v - __bfloat162float(hi));
}
__device__ __forceinline__ void split4(float4 v, uint2& hi, uint2& lo){
    __nv_bfloat16 hx, hy, hz, hw, lx, ly, lz, lw;
    split1(v.x, hx, lx); split1(v.y, hy, ly); split1(v.z, hz, lz); split1(v.w, hw, lw);
    __nv_bfloat162 h01; h01.x = hx; h01.y = hy;
    __nv_bfloat162 h23; h23.x = hz; h23.y = hw;
    __nv_bfloat162 l01; l01.x = lx; l01.y = ly;
    __nv_bfloat162 l23; l23.x = lz; l23.y = lw;
    hi.x = *reinterpret_cast<uint32_t*>(&h01); hi.y = *reinterpret_cast<uint32_t*>(&h23);
    lo.x = *reinterpret_cast<uint32_t*>(&l01); lo.y = *reinterpret_cast<uint32_t*>(&l23);
}

// -------- pre-kernel: split x into bf16 hi/lo --------
__global__ void __launch_bounds__(256)
split_x_kernel(const float* __restrict__ x)
{
    int i = blockIdx.x * 256 + threadIdx.x;
    float4 v = reinterpret_cast<const float4*>(x)[i];
    uint2 hi, lo; split4(v, hi, lo);
    reinterpret_cast<uint2*>(gx_hi)[i] = hi;
    reinterpret_cast<uint2*>(gx_lo)[i] = lo;
}

extern __shared__ char smem[];

// -------- main persistent kernel: fully decoupled layer pipelines --------
__global__ void __launch_bounds__(THREADS, 1) __cluster_dims__(CLUSTER_SIZE, 1, 1)
lstm_main_kernel(const float* __restrict__ W,
                 const float* __restrict__ U,
                 const float* __restrict__ bias,
                 float* __restrict__ out)
{
    const uint32_t sbase = smem_u32(smem);
    const int tid = threadIdx.x;
    const int wid = tid >> 5, lane = tid & 31;
    const uint32_t rank = cl_rank();
    const int m0 = (blockIdx.x >> 2) * MT;
    const int layer = wid >> 2;          // 0: layer1 warps, 1: layer2 warps
    const int ws = wid & 3;              // n32 cell-slice
    const int lt = tid & 127;            // index within layer group

    // ---- B build: n = gate*32 + cell_local, [128 n][512 B] swizzled (one-time)
    #pragma unroll
    for (int i = 0; i < 32; ++i){
        int tsk = tid + i * THREADS;
        int n = tsk >> 6, kq = tsk & 63, k = kq * 4;
        int gate = n >> 5, cell = n & 31;
        int col = gate * 128 + (int)rank * 32 + cell;
        float4 v;
        float* vv = reinterpret_cast<float*>(&v);
        #pragma unroll
        for (int j = 0; j < 4; ++j){
            int kk = k + j;
            vv[j] = (kk < 128) ? W[kk * 512 + col] : U[(kk - 128) * 512 + col];
        }
        uint2 hi, lo; split4(v, hi, lo);
        uint32_t so = n * 512 + ((((kq >> 1) ^ (n & 7)) << 4)) + ((kq & 1) << 3);
        *reinterpret_cast<uint2*>(smem + SM_BHI + so) = hi;
        *reinterpret_cast<uint2*>(smem + SM_BLO + so) = lo;
    }

    // ---- prefetch x(0) -> X slot0, x(1) -> X slot1 (all threads)
    #pragma unroll
    for (int slot = 0; slot < 2; ++slot){
        #pragma unroll
        for (int i = 0; i < 4; ++i){
            int idx = tid + i * THREADS;
            int pl = idx >> 9, r = (idx >> 4) & 31, u = idx & 15;
            const __nv_bfloat16* sp = (pl ? gx_lo : gx_hi)
                + ((size_t)(m0 + r) * TSTEPS + slot) * DDIM + u * 8;
            cpa16(sbase + SM_X + slot * 16384 + pl * 8192
                  + r * 256 + (((u ^ (r & 7)) << 4)), sp);
        }
        cp_commit();
    }

    // ---- per-warp coordinates: m32 x n32 tile
    const int a_row0 = lane & 15;
    const int a_row1 = a_row0 + 16;
    const uint32_t a0b = a_row0 * 256, a0x = (a_row0 & 7) << 4;
    const uint32_t a1b = a_row1 * 256, a1x = (a_row1 & 7) << 4;
    const uint32_t a_lk = (lane >> 4) << 4;
    const int n01 = ws * 8 + (lane & 7) + ((lane >> 4) << 5);
    const int n23 = n01 + 64;
    const uint32_t b01b = n01 * 512, b01x = (n01 & 7) << 4;
    const uint32_t b23b = n23 * 512, b23x = (n23 & 7) << 4;
    const uint32_t b_lk = ((lane >> 3) & 1) << 4;

    const int R0 = lane >> 2;                                 // local rows R0 + {0,8,16,24}
    const int gc = (int)rank * 32 + ws * 8 + (lane & 3) * 2;  // global cells gc, gc+1

    // ---- zero h2(0) own slice (layer2 warps)
    if (layer == 1){
        __nv_bfloat162 z; z.x = __float2bfloat16(0.f); z.y = z.x;
        #pragma unroll
        for (int rr = 0; rr < 4; ++rr){
            int r = m0 + R0 + rr * 8;
            *reinterpret_cast<__nv_bfloat162*>(&gh2[0][r * 256 + gc]) = z;
            *reinterpret_cast<__nv_bfloat162*>(&gh2[0][r * 256 + 128 + gc]) = z;
        }
    }

    float bia[4][2];
    #pragma unroll
    for (int g = 0; g < 4; ++g){
        bia[g][0] = bias[g * 128 + gc];
        bia[g][1] = bias[g * 128 + gc + 1];
    }

    float cst[8];                 // c1 (layer-1 warps) or c2 (layer-2 warps)
    #pragma unroll
    for (int j = 0; j < 8; ++j) cst[j] = 0.f;

    float acc[2][4][4];

    #define ACC_INIT()                                          \
        _Pragma("unroll")                                       \
        for (int mf = 0; mf < 2; ++mf)                          \
            _Pragma("unroll")                                   \
            for (int g = 0; g < 4; ++g){                        \
                acc[mf][g][0] = bia[g][0]; acc[mf][g][1] = bia[g][1]; \
                acc[mf][g][2] = bia[g][0]; acc[mf][g][3] = bia[g][1]; \
            }

    // full K=128 GEMM onto acc: A m32 from (AHI, ALO), B rows at +BOFS bytes
    #define MMA8(AHI, ALO, BOFS)                                                       \
    {                                                                                  \
        _Pragma("unroll")                                                              \
        for (int ks = 0; ks < 8; ++ks){                                                \
            uint32_t kbA = (uint32_t)(ks * 32) + a_lk;                                 \
            uint32_t kbB = (uint32_t)(ks * 32) + (uint32_t)(BOFS) + b_lk;              \
            uint32_t ah0[4], al0[4], ah1[4], al1[4], bh[8], bl[8];                     \
            ldsm4(ah0[0], ah0[1], ah0[2], ah0[3], (AHI) + a0b + (kbA ^ a0x));          \
            ldsm4(al0[0], al0[1], al0[2], al0[3], (ALO) + a0b + (kbA ^ a0x));          \
            ldsm4(ah1[0], ah1[1], ah1[2], ah1[3], (AHI) + a1b + (kbA ^ a1x));          \
            ldsm4(al1[0], al1[1], al1[2], al1[3], (ALO) + a1b + (kbA ^ a1x));          \
            ldsm4(bh[0], bh[1], bh[2], bh[3], sbase + SM_BHI + b01b + (kbB ^ b01x));   \
            ldsm4(bh[4], bh[5], bh[6], bh[7], sbase + SM_BHI + b23b + (kbB ^ b23x));   \
            ldsm4(bl[0], bl[1], bl[2], bl[3], sbase + SM_BLO + b01b + (kbB ^ b01x));   \
            ldsm4(bl[4], bl[5], bl[6], bl[7], sbase + SM_BLO + b23b + (kbB ^ b23x));   \
            _Pragma("unroll")                                                          \
            for (int g = 0; g < 4; ++g){                                               \
                hmma(acc[0][g], ah0, bh[g*2], bh[g*2+1]);                              \
                hmma(acc[0][g], ah0, bl[g*2], bl[g*2+1]);                              \
                hmma(acc[0][g], al0, bh[g*2], bh[g*2+1]);                              \
                hmma(acc[1][g], ah1, bh[g*2], bh[g*2+1]);                              \
                hmma(acc[1][g], ah1, bl[g*2], bl[g*2+1]);                              \
                hmma(acc[1][g], al1, bh[g*2], bh[g*2+1]);                              \
            }                                                                          \
        }                                                                              \
    }

    // issue a 16KB h-buffer readback with this layer's 128 threads
    #define ISSUE_H(DSTBASE, SRC)                                                     \
    {                                                                                 \
        _Pragma("unroll")                                                             \
        for (int i = 0; i < 8; ++i){                                                  \
            int idx = lt + i * 128;                                                   \
            int pl = idx >> 9, r = (idx >> 4) & 31, u = idx & 15;                     \
            cpa16((DSTBASE) + pl * 8192 + r * 256 + (((u ^ (r & 7)) << 4)),           \
                  &(SRC)[(m0 + r) * 256 + pl * 128 + u * 8]);                         \
        }                                                                             \
    }

    const uint32_t H1A = sbase + SM_H1A, H1C = sbase + SM_H1C, H2b = sbase + SM_H2;

    // ---- prologue: layer1 computes h1(1) = E1(bias + x(0)·W); publish to gh1[1]
    cp_wait<0>();
    __syncthreads();
    if (layer == 0){
        ACC_INIT();
        MMA8(sbase + SM_X, sbase + SM_X + 8192, 0);
        float hv[8];
        #pragma unroll
        for (int mf = 0; mf < 2; ++mf)
            #pragma unroll
            for (int v = 0; v < 4; ++v){
                int j = mf * 4 + v;
                float cn = fsig(acc[mf][1][v]) * cst[j]
                         + fsig(acc[mf][0][v]) * ftanh_(acc[mf][2][v]);
                cst[j] = cn;
                hv[j] = fsig(acc[mf][3][v]) * ftanh_(cn);
            }
        #pragma unroll
        for (int rr = 0; rr < 4; ++rr){
            int r = m0 + R0 + rr * 8;
            int j0 = (rr >> 1) * 4 + (rr & 1) * 2;
            __nv_bfloat162 hh, ll;
            split1(hv[j0], hh.x, ll.x);
            split1(hv[j0 + 1], hh.y, ll.y);
            *reinterpret_cast<__nv_bfloat162*>(&gh1[1][r * 256 + gc]) = hh;
            *reinterpret_cast<__nv_bfloat162*>(&gh1[1][r * 256 + 128 + gc]) = ll;
        }
    }
    cl_arrive();     // B_{-1}: h1(1), h2(0) published

    for (int t = 0; t < TSTEPS; ++t){
        const int s = t & 1, ns = s ^ 1;
        const uint32_t Xrd = sbase + SM_X + ns * 16384;   // x(t+1)
        const uint32_t Xwr = sbase + SM_X + s * 16384;    // refill x(t+2)

        cl_wait();   // B_{t-1}: h1(t+1) [gh1[ns]] and h2(t) [gh2[s]] visible

        if (layer == 0){
            // ========= LAYER-1 pipeline (independent of layer-2) =========
            ISSUE_H(H1A, gh1[ns]);           // h1(t+1) -> private copy
            cp_commit();
            if (t + 2 < TSTEPS){             // X refill
                #pragma unroll
                for (int i = 0; i < 8; ++i){
                    int idx = lt + i * 128;
                    int pl = idx >> 9, r = (idx >> 4) & 31, u = idx & 15;
                    const __nv_bfloat16* sp = (pl ? gx_lo : gx_hi)
                        + ((size_t)(m0 + r) * TSTEPS + (t + 2)) * DDIM + u * 8;
                    cpa16(Xwr + pl * 8192 + r * 256 + (((u ^ (r & 7)) << 4)), sp);
                }
            }
            cp_commit();

            ACC_INIT();
            cp_wait<2>();                    // prev step's X refill retired
            barn(1);                         // Xrd complete CTA-group-wide
            if (t + 1 < TSTEPS){
                MMA8(Xrd, Xrd + 8192, 0);    // z1(t+1) += x(t+1)·W  (covers H1A)
            }
            cp_wait<1>();                    // H1A done (mine)
            barn(1);                         // H1A done (all L1 threads)
            MMA8(H1A, H1A + 8192, 256);      // z1(t+1) += h1(t+1)·U

            // E1 -> h1(t+2) -> gh1[s]
            float hv[8];
            #pragma unroll
            for (int mf = 0; mf < 2; ++mf)
                #pragma unroll
                for (int v = 0; v < 4; ++v){
                    int j = mf * 4 + v;
                    float cn = fsig(acc[mf][1][v]) * cst[j]
                             + fsig(acc[mf][0][v]) * ftanh_(acc[mf][2][v]);
                    cst[j] = cn;
                    hv[j] = fsig(acc[mf][3][v]) * ftanh_(cn);
                }
            #pragma unroll
            for (int rr = 0; rr < 4; ++rr){
                int r = m0 + R0 + rr * 8;
                int j0 = (rr >> 1) * 4 + (rr & 1) * 2;
                __nv_bfloat162 hh, ll;
                split1(hv[j0], hh.x, ll.x);
                split1(hv[j0 + 1], hh.y, ll.y);
                *reinterpret_cast<__nv_bfloat162*>(&gh1[s][r * 256 + gc]) = hh;
                *reinterpret_cast<__nv_bfloat162*>(&gh1[s][r * 256 + 128 + gc]) = ll;
            }
        } else {
            // ========= LAYER-2 pipeline =========
            ISSUE_H(H2b, gh2[s]);            // h2(t)
            cp_commit();
            ISSUE_H(H1C, gh1[ns]);           // h1(t+1) -> private copy
            cp_commit();

            ACC_INIT();
            cp_wait<1>();                    // H2b done (mine)
            barn(2);                         // H2b done (all L2 threads)
            MMA8(H2b, H2b + 8192, 256);      // z2 += h2(t)·U  (covers H1C)
            cp_wait<0>();                    // H1C done (mine)
            barn(2);
            MMA8(H1C, H1C + 8192, 0);        // z2 += h1(t+1)·W

            // residual h1(t+1) from H1C (hi+lo reconstruct)
            float res[8];
            #pragma unroll
            for (int rr = 0; rr < 4; ++rr){
                int rloc = R0 + rr * 8;
                uint32_t ho = (uint32_t)(rloc * 256
                            + ((((uint32_t)(gc >> 3) ^ (uint32_t)(rloc & 7))) << 4)
                            + ((2 * gc) & 15));
                __nv_bfloat162 hh = *reinterpret_cast<const __nv_bfloat162*>(smem + SM_H1C + ho);
                __nv_bfloat162 ll = *reinterpret_cast<const __nv_bfloat162*>(smem + SM_H1C + 8192 + ho);
                res[rr * 2 + 0] = __bfloat162float(hh.x) + __bfloat162float(ll.x);
                res[rr * 2 + 1] = __bfloat162float(hh.y) + __bfloat162float(ll.y);
            }
            float hv[8];
            #pragma unroll
            for (int mf = 0; mf < 2; ++mf)
                #pragma unroll
                for (int v = 0; v < 4; ++v){
                    int j = mf * 4 + v;
                    float cn = fsig(acc[mf][1][v]) * cst[j]
                             + fsig(acc[mf][0][v]) * ftanh_(acc[mf][2][v]);
                    cst[j] = cn;
                    hv[j] = fsig(acc[mf][3][v]) * ftanh_(cn);
                }
            #pragma unroll
            for (int rr = 0; rr < 4; ++rr){
                int rloc = R0 + rr * 8;
                int r = m0 + rloc;
                int j0 = (rr >> 1) * 4 + (rr & 1) * 2;
                float h0 = hv[j0] + res[rr * 2 + 0];      // + residual h1(t+1)
                float h1v = hv[j0 + 1] + res[rr * 2 + 1];
                __nv_bfloat162 hh, ll;
                split1(h0, hh.x, ll.x);
                split1(h1v, hh.y, ll.y);
                *reinterpret_cast<__nv_bfloat162*>(&gh2[ns][r * 256 + gc]) = hh;
                *reinterpret_cast<__nv_bfloat162*>(&gh2[ns][r * 256 + 128 + gc]) = ll;
                float2 ov; ov.x = h0; ov.y = h1v;
                *reinterpret_cast<float2*>(&out[((size_t)r * TSTEPS + t) * DDIM + gc]) = ov;
            }
        }

        cl_arrive();     // B_t: h1(t+2) + h2(t+1) published
    }
    cl_wait();           // consume final arrive

    #undef ISSUE_H
    #undef MMA8
    #undef ACC_INIT
}

extern "C" void kernel_launch(void* const* d_in, const int* in_sizes, int n_in,
                              void* d_out, int out_size)
{
    const float* x    = (const float*)d_in[0];
    const float* W    = (const float*)d_in[1];
    const float* U    = (const float*)d_in[2];
    const float* bias = (const float*)d_in[3];
    // d_in[4] = seq_len: reference ignores it
    float* out = (float*)d_out;

    split_x_kernel<<<(BATCH * TSTEPS * DDIM / 4) / 256, 256>>>(x);

    cudaFuncSetAttribute(lstm_main_kernel,
                         cudaFuncAttributeMaxDynamicSharedMemorySize, SMEM_MAIN);
    lstm_main_kernel<<<128, THREADS, SMEM_MAIN>>>(W, U, bias, out);
}

// round 15
// speedup vs baseline: 1.3354x; 1.0257x over previous
#include <cuda_runtime.h>
#include <cuda_bf16.h>
#include <cstdint>

// Problem dims
#define BATCH 1024
#define TSTEPS 200
#define DDIM 128

#define THREADS 256
#define CLUSTER_SIZE 4
#define MT 32                     // batch rows per cluster

// SMEM layout (bytes)
#define SM_BHI 0                  // [128 n][512 B]
#define SM_BLO 65536
#define SM_H1A 131072             // L1's h1(t+1) copy: 16 KB (hi 8K + lo 8K)
#define SM_H1C 147456             // L2's h1(t+1) copy: 16 KB
#define SM_H2  163840             // 16 KB
#define SM_X   180224             // 2 slots x 16 KB
#define SMEM_MAIN 212992

// device globals (no allocation allowed)
__device__ __nv_bfloat16 gx_hi[(size_t)BATCH*TSTEPS*DDIM];
__device__ __nv_bfloat16 gx_lo[(size_t)BATCH*TSTEPS*DDIM];
__device__ __nv_bfloat16 gh1[2][BATCH*256];  // [slot][row*256 + plane*128 + cell]
__device__ __nv_bfloat16 gh2[2][BATCH*256];

// ---------------- helpers ----------------
__device__ __forceinline__ uint32_t smem_u32(const void* p){
    uint32_t a;
    asm("{ .reg .u64 t; cvta.to.shared.u64 t, %1; cvt.u32.u64 %0, t; }" : "=r"(a) : "l"(p));
    return a;
}
__device__ __forceinline__ uint32_t cl_rank(){
    uint32_t r; asm("mov.u32 %0, %%cluster_ctarank;" : "=r"(r)); return r;
}
__device__ __forceinline__ void cl_arrive(){ asm volatile("barrier.cluster.arrive.aligned;" ::: "memory"); }
__device__ __forceinline__ void cl_wait(){ asm volatile("barrier.cluster.wait.aligned;" ::: "memory"); }
__device__ __forceinline__ void barn(int id){ asm volatile("bar.sync %0, 128;" :: "r"(id) : "memory"); }
__device__ __forceinline__ void cpa16(uint32_t dst, const void* src){
    asm volatile("cp.async.cg.shared.global [%0], [%1], 16;" :: "r"(dst), "l"(src));
}
__device__ __forceinline__ void cp_commit(){ asm volatile("cp.async.commit_group;" ::: "memory"); }
template<int N> __device__ __forceinline__ void cp_wait(){ asm volatile("cp.async.wait_group %0;" :: "n"(N) : "memory"); }

__device__ __forceinline__ void ldsm4(uint32_t& r0, uint32_t& r1, uint32_t& r2, uint32_t& r3, uint32_t addr){
    asm volatile("ldmatrix.sync.aligned.m8n8.x4.shared.b16 {%0,%1,%2,%3}, [%4];"
                 : "=r"(r0), "=r"(r1), "=r"(r2), "=r"(r3) : "r"(addr));
}
__device__ __forceinline__ void hmma(float* c, const uint32_t* a, uint32_t b0, uint32_t b1){
    asm volatile("mma.sync.aligned.m16n8k16.row.col.f32.bf16.bf16.f32 "
                 "{%0,%1,%2,%3}, {%4,%5,%6,%7}, {%8,%9}, {%0,%1,%2,%3};"
                 : "+f"(c[0]), "+f"(c[1]), "+f"(c[2]), "+f"(c[3])
                 : "r"(a[0]), "r"(a[1]), "r"(a[2]), "r"(a[3]), "r"(b0), "r"(b1));
}
__device__ __forceinline__ float fsig(float x){ return __fdividef(1.f, 1.f + __expf(-x)); }
__device__ __forceinline__ float ftanh_(float x){
    x = fminf(15.f, fmaxf(-15.f, x));
    float e = __expf(2.f * x);
    return __fdividef(e - 1.f, e + 1.f);
}
__device__ __forceinline__ void split1(float v, __nv_bfloat16& hi, __nv_bfloat16& lo){
    hi = __float2bfloat16(v);
    lo = __float2bfloat16(v - __bfloat162float(hi));
}
__device__ __forceinline__ void split4(float4 v, uint2& hi, uint2& lo){
    __nv_bfloat16 hx, hy, hz, hw, lx, ly, lz, lw;
    split1(v.x, hx, lx); split1(v.y, hy, ly); split1(v.z, hz, lz); split1(v.w, hw, lw);
    __nv_bfloat162 h01; h01.x = hx; h01.y = hy;
    __nv_bfloat162 h23; h23.x = hz; h23.y = hw;
    __nv_bfloat162 l01; l01.x = lx; l01.y = ly;
    __nv_bfloat162 l23; l23.x = lz; l23.y = lw;
    hi.x = *reinterpret_cast<uint32_t*>(&h01); hi.y = *reinterpret_cast<uint32_t*>(&h23);
    lo.x = *reinterpret_cast<uint32_t*>(&l01); lo.y = *reinterpret_cast<uint32_t*>(&l23);
}

// -------- pre-kernel: split x into bf16 hi/lo --------
__global__ void __launch_bounds__(256)
split_x_kernel(const float* __restrict__ x)
{
    int i = blockIdx.x * 256 + threadIdx.x;
    float4 v = reinterpret_cast<const float4*>(x)[i];
    uint2 hi, lo; split4(v, hi, lo);
    reinterpret_cast<uint2*>(gx_hi)[i] = hi;
    reinterpret_cast<uint2*>(gx_lo)[i] = lo;
}

extern __shared__ char smem[];

// -------- main persistent kernel: hoisted x-GEMM fills the barrier window --------
__global__ void __launch_bounds__(THREADS, 1) __cluster_dims__(CLUSTER_SIZE, 1, 1)
lstm_main_kernel(const float* __restrict__ W,
                 const float* __restrict__ U,
                 const float* __restrict__ bias,
                 float* __restrict__ out)
{
    const uint32_t sbase = smem_u32(smem);
    const int tid = threadIdx.x;
    const int wid = tid >> 5, lane = tid & 31;
    const uint32_t rank = cl_rank();
    const int m0 = (blockIdx.x >> 2) * MT;
    const int layer = wid >> 2;          // 0: layer1 warps, 1: layer2 warps
    const int ws = wid & 3;              // n32 cell-slice
    const int lt = tid & 127;            // index within layer group

    // ---- B build: n = gate*32 + cell_local, [128 n][512 B] swizzled (one-time)
    #pragma unroll
    for (int i = 0; i < 32; ++i){
        int tsk = tid + i * THREADS;
        int n = tsk >> 6, kq = tsk & 63, k = kq * 4;
        int gate = n >> 5, cell = n & 31;
        int col = gate * 128 + (int)rank * 32 + cell;
        float4 v;
        float* vv = reinterpret_cast<float*>(&v);
        #pragma unroll
        for (int j = 0; j < 4; ++j){
            int kk = k + j;
            vv[j] = (kk < 128) ? W[kk * 512 + col] : U[(kk - 128) * 512 + col];
        }
        uint2 hi, lo; split4(v, hi, lo);
        uint32_t so = n * 512 + ((((kq >> 1) ^ (n & 7)) << 4)) + ((kq & 1) << 3);
        *reinterpret_cast<uint2*>(smem + SM_BHI + so) = hi;
        *reinterpret_cast<uint2*>(smem + SM_BLO + so) = lo;
    }

    // ---- prefetch x(0) -> X slot0, x(1) -> X slot1 (all threads)
    #pragma unroll
    for (int slot = 0; slot < 2; ++slot){
        #pragma unroll
        for (int i = 0; i < 4; ++i){
            int idx = tid + i * THREADS;
            int pl = idx >> 9, r = (idx >> 4) & 31, u = idx & 15;
            const __nv_bfloat16* sp = (pl ? gx_lo : gx_hi)
                + ((size_t)(m0 + r) * TSTEPS + slot) * DDIM + u * 8;
            cpa16(sbase + SM_X + slot * 16384 + pl * 8192
                  + r * 256 + (((u ^ (r & 7)) << 4)), sp);
        }
        cp_commit();
    }

    // ---- per-warp coordinates: m32 x n32 tile
    const int a_row0 = lane & 15;
    const int a_row1 = a_row0 + 16;
    const uint32_t a0b = a_row0 * 256, a0x = (a_row0 & 7) << 4;
    const uint32_t a1b = a_row1 * 256, a1x = (a_row1 & 7) << 4;
    const uint32_t a_lk = (lane >> 4) << 4;
    const int n01 = ws * 8 + (lane & 7) + ((lane >> 4) << 5);
    const int n23 = n01 + 64;
    const uint32_t b01b = n01 * 512, b01x = (n01 & 7) << 4;
    const uint32_t b23b = n23 * 512, b23x = (n23 & 7) << 4;
    const uint32_t b_lk = ((lane >> 3) & 1) << 4;

    const int R0 = lane >> 2;                                 // local rows R0 + {0,8,16,24}
    const int gc = (int)rank * 32 + ws * 8 + (lane & 3) * 2;  // global cells gc, gc+1

    // ---- zero h2(0) own slice (layer2 warps)
    if (layer == 1){
        __nv_bfloat162 z; z.x = __float2bfloat16(0.f); z.y = z.x;
        #pragma unroll
        for (int rr = 0; rr < 4; ++rr){
            int r = m0 + R0 + rr * 8;
            *reinterpret_cast<__nv_bfloat162*>(&gh2[0][r * 256 + gc]) = z;
            *reinterpret_cast<__nv_bfloat162*>(&gh2[0][r * 256 + 128 + gc]) = z;
        }
    }

    float bia[4][2];
    #pragma unroll
    for (int g = 0; g < 4; ++g){
        bia[g][0] = bias[g * 128 + gc];
        bia[g][1] = bias[g * 128 + gc + 1];
    }

    float cst[8];                 // c1 (layer-1 warps) or c2 (layer-2 warps)
    #pragma unroll
    for (int j = 0; j < 8; ++j) cst[j] = 0.f;

    float acc[2][4][4];

    #define ACC_INIT()                                          \
        _Pragma("unroll")                                       \
        for (int mf = 0; mf < 2; ++mf)                          \
            _Pragma("unroll")                                   \
            for (int g = 0; g < 4; ++g){                        \
                acc[mf][g][0] = bia[g][0]; acc[mf][g][1] = bia[g][1]; \
                acc[mf][g][2] = bia[g][0]; acc[mf][g][3] = bia[g][1]; \
            }

    // full K=128 GEMM onto acc: A m32 from (AHI, ALO), B rows at +BOFS bytes
    #define MMA8(AHI, ALO, BOFS)                                                       \
    {                                                                                  \
        _Pragma("unroll")                                                              \
        for (int ks = 0; ks < 8; ++ks){                                                \
            uint32_t kbA = (uint32_t)(ks * 32) + a_lk;                                 \
            uint32_t kbB = (uint32_t)(ks * 32) + (uint32_t)(BOFS) + b_lk;              \
            uint32_t ah0[4], al0[4], ah1[4], al1[4], bh[8], bl[8];                     \
            ldsm4(ah0[0], ah0[1], ah0[2], ah0[3], (AHI) + a0b + (kbA ^ a0x));          \
            ldsm4(al0[0], al0[1], al0[2], al0[3], (ALO) + a0b + (kbA ^ a0x));          \
            ldsm4(ah1[0], ah1[1], ah1[2], ah1[3], (AHI) + a1b + (kbA ^ a1x));          \
            ldsm4(al1[0], al1[1], al1[2], al1[3], (ALO) + a1b + (kbA ^ a1x));          \
            ldsm4(bh[0], bh[1], bh[2], bh[3], sbase + SM_BHI + b01b + (kbB ^ b01x));   \
            ldsm4(bh[4], bh[5], bh[6], bh[7], sbase + SM_BHI + b23b + (kbB ^ b23x));   \
            ldsm4(bl[0], bl[1], bl[2], bl[3], sbase + SM_BLO + b01b + (kbB ^ b01x));   \
            ldsm4(bl[4], bl[5], bl[6], bl[7], sbase + SM_BLO + b23b + (kbB ^ b23x));   \
            _Pragma("unroll")                                                          \
            for (int g = 0; g < 4; ++g){                                               \
                hmma(acc[0][g], ah0, bh[g*2], bh[g*2+1]);                              \
                hmma(acc[0][g], ah0, bl[g*2], bl[g*2+1]);                              \
                hmma(acc[0][g], al0, bh[g*2], bh[g*2+1]);                              \
                hmma(acc[1][g], ah1, bh[g*2], bh[g*2+1]);                              \
                hmma(acc[1][g], ah1, bl[g*2], bl[g*2+1]);                              \
                hmma(acc[1][g], al1, bh[g*2], bh[g*2+1]);                              \
            }                                                                          \
        }                                                                              \
    }

    // issue a 16KB h-buffer readback with this layer's 128 threads
    #define ISSUE_H(DSTBASE, SRC)                                                     \
    {                                                                                 \
        _Pragma("unroll")                                                             \
        for (int i = 0; i < 8; ++i){                                                  \
            int idx = lt + i * 128;                                                   \
            int pl = idx >> 9, r = (idx >> 4) & 31, u = idx & 15;                     \
            cpa16((DSTBASE) + pl * 8192 + r * 256 + (((u ^ (r & 7)) << 4)),           \
                  &(SRC)[(m0 + r) * 256 + pl * 128 + u * 8]);                         \
        }                                                                             \
    }

    const uint32_t H1A = sbase + SM_H1A, H1C = sbase + SM_H1C, H2b = sbase + SM_H2;

    // ---- prologue: layer1 computes h1(1) = E1(bias + x(0)·W); publish to gh1[1]
    cp_wait<0>();
    __syncthreads();
    if (layer == 0){
        ACC_INIT();
        MMA8(sbase + SM_X, sbase + SM_X + 8192, 0);
        float hv[8];
        #pragma unroll
        for (int mf = 0; mf < 2; ++mf)
            #pragma unroll
            for (int v = 0; v < 4; ++v){
                int j = mf * 4 + v;
                float cn = fsig(acc[mf][1][v]) * cst[j]
                         + fsig(acc[mf][0][v]) * ftanh_(acc[mf][2][v]);
                cst[j] = cn;
                hv[j] = fsig(acc[mf][3][v]) * ftanh_(cn);
            }
        #pragma unroll
        for (int rr = 0; rr < 4; ++rr){
            int r = m0 + R0 + rr * 8;
            int j0 = (rr >> 1) * 4 + (rr & 1) * 2;
            __nv_bfloat162 hh, ll;
            split1(hv[j0], hh.x, ll.x);
            split1(hv[j0 + 1], hh.y, ll.y);
            *reinterpret_cast<__nv_bfloat162*>(&gh1[1][r * 256 + gc]) = hh;
            *reinterpret_cast<__nv_bfloat162*>(&gh1[1][r * 256 + 128 + gc]) = ll;
        }
    }
    cl_arrive();     // B_{-1}: h1(1), h2(0) published

    for (int t = 0; t < TSTEPS; ++t){
        const int s = t & 1, ns = s ^ 1;
        const uint32_t Xrd = sbase + SM_X + ns * 16384;   // x(t+1)
        const uint32_t Xwr = sbase + SM_X + s * 16384;    // refill x(t+2)

        // ===== PRE-WAIT zone: barrier-independent work fills the skew window =====
        ACC_INIT();
        if (layer == 0){
            cp_wait<0>();                // all own prior groups retired (incl. x(t+1) refill)
            barn(1);                     // Xrd complete across all L1 threads
            if (t + 1 < TSTEPS){
                MMA8(Xrd, Xrd + 8192, 0);    // z1(t+1) += x(t+1)·W
            }
        }

        cl_wait();   // B_{t-1}: h1(t+1) [gh1[ns]] and h2(t) [gh2[s]] visible

        if (layer == 0){
            // ========= LAYER-1 post-wait =========
            ISSUE_H(H1A, gh1[ns]);           // h1(t+1) -> private copy
            cp_commit();
            if (t + 2 < TSTEPS){             // X refill x(t+2) -> slot s
                #pragma unroll
                for (int i = 0; i < 8; ++i){
                    int idx = lt + i * 128;
                    int pl = idx >> 9, r = (idx >> 4) & 31, u = idx & 15;
                    const __nv_bfloat16* sp = (pl ? gx_lo : gx_hi)
                        + ((size_t)(m0 + r) * TSTEPS + (t + 2)) * DDIM + u * 8;
                    cpa16(Xwr + pl * 8192 + r * 256 + (((u ^ (r & 7)) << 4)), sp);
                }
            }
            cp_commit();

            cp_wait<1>();                    // H1A done (mine); X refill still in flight
            barn(1);                         // H1A done (all L1 threads)
            MMA8(H1A, H1A + 8192, 256);      // z1(t+1) += h1(t+1)·U

            // E1 -> h1(t+2) -> gh1[s]
            float hv[8];
            #pragma unroll
            for (int mf = 0; mf < 2; ++mf)
                #pragma unroll
                for (int v = 0; v < 4; ++v){
                    int j = mf * 4 + v;
                    float cn = fsig(acc[mf][1][v]) * cst[j]
                             + fsig(acc[mf][0][v]) * ftanh_(acc[mf][2][v]);
                    cst[j] = cn;
                    hv[j] = fsig(acc[mf][3][v]) * ftanh_(cn);
                }
            #pragma unroll
            for (int rr = 0; rr < 4; ++rr){
                int r = m0 + R0 + rr * 8;
                int j0 = (rr >> 1) * 4 + (rr & 1) * 2;
                __nv_bfloat162 hh, ll;
                split1(hv[j0], hh.x, ll.x);
                split1(hv[j0 + 1], hh.y, ll.y);
                *reinterpret_cast<__nv_bfloat162*>(&gh1[s][r * 256 + gc]) = hh;
                *reinterpret_cast<__nv_bfloat162*>(&gh1[s][r * 256 + 128 + gc]) = ll;
            }
        } else {
            // ========= LAYER-2 post-wait =========
            ISSUE_H(H2b, gh2[s]);            // h2(t)
            cp_commit();
            ISSUE_H(H1C, gh1[ns]);           // h1(t+1) -> private copy
            cp_commit();

            cp_wait<1>();                    // H2b done (mine)
            barn(2);                         // H2b done (all L2 threads)
            MMA8(H2b, H2b + 8192, 256);      // z2 += h2(t)·U  (covers H1C)
            cp_wait<0>();                    // H1C done (mine)
            barn(2);
            MMA8(H1C, H1C + 8192, 0);        // z2 += h1(t+1)·W

            // residual h1(t+1) from H1C (hi+lo reconstruct)
            float res[8];
            #pragma unroll
            for (int rr = 0; rr < 4; ++rr){
                int rloc = R0 + rr * 8;
                uint32_t ho = (uint32_t)(rloc * 256
                            + ((((uint32_t)(gc >> 3) ^ (uint32_t)(rloc & 7))) << 4)
                            + ((2 * gc) & 15));
                __nv_bfloat162 hh = *reinterpret_cast<const __nv_bfloat162*>(smem + SM_H1C + ho);
                __nv_bfloat162 ll = *reinterpret_cast<const __nv_bfloat162*>(smem + SM_H1C + 8192 + ho);
                res[rr * 2 + 0] = __bfloat162float(hh.x) + __bfloat162float(ll.x);
                res[rr * 2 + 1] = __bfloat162float(hh.y) + __bfloat162float(ll.y);
            }
            float hv[8];
            #pragma unroll
            for (int mf = 0; mf < 2; ++mf)
                #pragma unroll
                for (int v = 0; v < 4; ++v){
                    int j = mf * 4 + v;
                    float cn = fsig(acc[mf][1][v]) * cst[j]
                             + fsig(acc[mf][0][v]) * ftanh_(acc[mf][2][v]);
                    cst[j] = cn;
                    hv[j] = fsig(acc[mf][3][v]) * ftanh_(cn);
                }
            #pragma unroll
            for (int rr = 0; rr < 4; ++rr){
                int rloc = R0 + rr * 8;
                int r = m0 + rloc;
                int j0 = (rr >> 1) * 4 + (rr & 1) * 2;
                float h0 = hv[j0] + res[rr * 2 + 0];      // + residual h1(t+1)
                float h1v = hv[j0 + 1] + res[rr * 2 + 1];
                __nv_bfloat162 hh, ll;
                split1(h0, hh.x, ll.x);
                split1(h1v, hh.y, ll.y);
                *reinterpret_cast<__nv_bfloat162*>(&gh2[ns][r * 256 + gc]) = hh;
                *reinterpret_cast<__nv_bfloat162*>(&gh2[ns][r * 256 + 128 + gc]) = ll;
                float2 ov; ov.x = h0; ov.y = h1v;
                *reinterpret_cast<float2*>(&out[((size_t)r * TSTEPS + t) * DDIM + gc]) = ov;
            }
        }

        cl_arrive();     // B_t: h1(t+2) + h2(t+1) published
    }
    cl_wait();           // consume final arrive

    #undef ISSUE_H
    #undef MMA8
    #undef ACC_INIT
}

extern "C" void kernel_launch(void* const* d_in, const int* in_sizes, int n_in,
                              void* d_out, int out_size)
{
    const float* x    = (const float*)d_in[0];
    const float* W    = (const float*)d_in[1];
    const float* U    = (const float*)d_in[2];
    const float* bias = (const float*)d_in[3];
    // d_in[4] = seq_len: reference ignores it
    float* out = (float*)d_out;

    split_x_kernel<<<(BATCH * TSTEPS * DDIM / 4) / 256, 256>>>(x);

    cudaFuncSetAttribute(lstm_main_kernel,
                         cudaFuncAttributeMaxDynamicSharedMemorySize, SMEM_MAIN);
    lstm_main_kernel<<<128, THREADS, SMEM_MAIN>>>(W, U, bias, out);
}

// round 16
// speedup vs baseline: 1.3620x; 1.0199x over previous
#include <cuda_runtime.h>
#include <cuda_bf16.h>
#include <cstdint>

// Problem dims
#define BATCH 1024
#define TSTEPS 200
#define DDIM 128

#define THREADS 512
#define CLUSTER_SIZE 4
#define MT 32                     // batch rows per cluster

// SMEM layout (bytes)
#define SM_BHI 0                  // [128 n][512 B]
#define SM_BLO 65536
#define SM_H1A 131072             // L1's h1(t+1) copy: 16 KB (hi 8K + lo 8K)
#define SM_H1C 147456             // L2's h1(t+1) copy: 16 KB
#define SM_H2  163840             // 16 KB
#define SM_X   180224             // 2 slots x 16 KB
#define SMEM_MAIN 212992

// device globals (no allocation allowed)
__device__ __nv_bfloat16 gx_hi[(size_t)BATCH*TSTEPS*DDIM];
__device__ __nv_bfloat16 gx_lo[(size_t)BATCH*TSTEPS*DDIM];
__device__ __nv_bfloat16 gh1[2][BATCH*256];  // [slot][row*256 + plane*128 + cell]
__device__ __nv_bfloat16 gh2[2][BATCH*256];

// ---------------- helpers ----------------
__device__ __forceinline__ uint32_t smem_u32(const void* p){
    uint32_t a;
    asm("{ .reg .u64 t; cvta.to.shared.u64 t, %1; cvt.u32.u64 %0, t; }" : "=r"(a) : "l"(p));
    return a;
}
__device__ __forceinline__ uint32_t cl_rank(){
    uint32_t r; asm("mov.u32 %0, %%cluster_ctarank;" : "=r"(r)); return r;
}
__device__ __forceinline__ void cl_arrive(){ asm volatile("barrier.cluster.arrive.aligned;" ::: "memory"); }
__device__ __forceinline__ void cl_wait(){ asm volatile("barrier.cluster.wait.aligned;" ::: "memory"); }
__device__ __forceinline__ void barn(int id){ asm volatile("bar.sync %0, 256;" :: "r"(id) : "memory"); }
__device__ __forceinline__ void cpa16(uint32_t dst, const void* src){
    asm volatile("cp.async.cg.shared.global [%0], [%1], 16;" :: "r"(dst), "l"(src));
}
__device__ __forceinline__ void cp_commit(){ asm volatile("cp.async.commit_group;" ::: "memory"); }
template<int N> __device__ __forceinline__ void cp_wait(){ asm volatile("cp.async.wait_group %0;" :: "n"(N) : "memory"); }

__device__ __forceinline__ void ldsm4(uint32_t& r0, uint32_t& r1, uint32_t& r2, uint32_t& r3, uint32_t addr){
    asm volatile("ldmatrix.sync.aligned.m8n8.x4.shared.b16 {%0,%1,%2,%3}, [%4];"
                 : "=r"(r0), "=r"(r1), "=r"(r2), "=r"(r3) : "r"(addr));
}
__device__ __forceinline__ void hmma(float* c, const uint32_t* a, uint32_t b0, uint32_t b1){
    asm volatile("mma.sync.aligned.m16n8k16.row.col.f32.bf16.bf16.f32 "
                 "{%0,%1,%2,%3}, {%4,%5,%6,%7}, {%8,%9}, {%0,%1,%2,%3};"
                 : "+f"(c[0]), "+f"(c[1]), "+f"(c[2]), "+f"(c[3])
                 : "r"(a[0]), "r"(a[1]), "r"(a[2]), "r"(a[3]), "r"(b0), "r"(b1));
}
__device__ __forceinline__ float fsig(float x){ return __fdividef(1.f, 1.f + __expf(-x)); }
__device__ __forceinline__ float ftanh_(float x){
    x = fminf(15.f, fmaxf(-15.f, x));
    float e = __expf(2.f * x);
    return __fdividef(e - 1.f, e + 1.f);
}
__device__ __forceinline__ void split1(float v, __nv_bfloat16& hi, __nv_bfloat16& lo){
    hi = __float2bfloat16(v);
    lo = __float2bfloat16(v - __bfloat162float(hi));
}
__device__ __forceinline__ void split4(float4 v, uint2& hi, uint2& lo){
    __nv_bfloat16 hx, hy, hz, hw, lx, ly, lz, lw;
    split1(v.x, hx, lx); split1(v.y, hy, ly); split1(v.z, hz, lz); split1(v.w, hw, lw);
    __nv_bfloat162 h01; h01.x = hx; h01.y = hy;
    __nv_bfloat162 h23; h23.x = hz; h23.y = hw;
    __nv_bfloat162 l01; l01.x = lx; l01.y = ly;
    __nv_bfloat162 l23; l23.x = lz; l23.y = lw;
    hi.x = *reinterpret_cast<uint32_t*>(&h01); hi.y = *reinterpret_cast<uint32_t*>(&h23);
    lo.x = *reinterpret_cast<uint32_t*>(&l01); lo.y = *reinterpret_cast<uint32_t*>(&l23);
}

// -------- pre-kernel: split x into bf16 hi/lo --------
__global__ void __launch_bounds__(256)
split_x_kernel(const float* __restrict__ x)
{
    int i = blockIdx.x * 256 + threadIdx.x;
    float4 v = reinterpret_cast<const float4*>(x)[i];
    uint2 hi, lo; split4(v, hi, lo);
    reinterpret_cast<uint2*>(gx_hi)[i] = hi;
    reinterpret_cast<uint2*>(gx_lo)[i] = lo;
}

extern __shared__ char smem[];

// -------- main persistent kernel: 16 warps, m16n32 tiles, layer-per-8-warps --------
__global__ void __launch_bounds__(THREADS, 1) __cluster_dims__(CLUSTER_SIZE, 1, 1)
lstm_main_kernel(const float* __restrict__ W,
                 const float* __restrict__ U,
                 const float* __restrict__ bias,
                 float* __restrict__ out)
{
    const uint32_t sbase = smem_u32(smem);
    const int tid = threadIdx.x;
    const int wid = tid >> 5, lane = tid & 31;
    const uint32_t rank = cl_rank();
    const int m0 = (blockIdx.x >> 2) * MT;
    const int layer = wid >> 3;          // 0: warps 0-7 (layer1), 1: warps 8-15 (layer2)
    const int lw = wid & 7;              // warp within layer
    const int mhalf = lw & 1;            // m16 half (rows 0-15 / 16-31)
    const int ws = lw >> 1;              // n32 cell-slice (0..3)
    const int lt = tid & 255;            // index within layer group (256 threads)

    // ---- B build: n = gate*32 + cell_local, [128 n][512 B] swizzled (one-time)
    #pragma unroll
    for (int i = 0; i < 16; ++i){
        int tsk = tid + i * THREADS;
        int n = tsk >> 6, kq = tsk & 63, k = kq * 4;
        int gate = n >> 5, cell = n & 31;
        int col = gate * 128 + (int)rank * 32 + cell;
        float4 v;
        float* vv = reinterpret_cast<float*>(&v);
        #pragma unroll
        for (int j = 0; j < 4; ++j){
            int kk = k + j;
            vv[j] = (kk < 128) ? W[kk * 512 + col] : U[(kk - 128) * 512 + col];
        }
        uint2 hi, lo; split4(v, hi, lo);
        uint32_t so = n * 512 + ((((kq >> 1) ^ (n & 7)) << 4)) + ((kq & 1) << 3);
        *reinterpret_cast<uint2*>(smem + SM_BHI + so) = hi;
        *reinterpret_cast<uint2*>(smem + SM_BLO + so) = lo;
    }

    // ---- prefetch x(0) -> X slot0, x(1) -> X slot1 (all threads)
    #pragma unroll
    for (int slot = 0; slot < 2; ++slot){
        #pragma unroll
        for (int i = 0; i < 2; ++i){
            int idx = tid + i * THREADS;
            int pl = idx >> 9, r = (idx >> 4) & 31, u = idx & 15;
            const __nv_bfloat16* sp = (pl ? gx_lo : gx_hi)
                + ((size_t)(m0 + r) * TSTEPS + slot) * DDIM + u * 8;
            cpa16(sbase + SM_X + slot * 16384 + pl * 8192
                  + r * 256 + (((u ^ (r & 7)) << 4)), sp);
        }
        cp_commit();
    }

    // ---- per-warp coordinates: m16 x n32 tile
    const int a_row = mhalf * 16 + (lane & 15);
    const uint32_t a_base = a_row * 256;
    const uint32_t a_xor = (a_row & 7) << 4;
    const uint32_t a_lk = (lane >> 4) << 4;
    const int n01 = ws * 8 + (lane & 7) + ((lane >> 4) << 5);
    const int n23 = n01 + 64;
    const uint32_t b01b = n01 * 512, b01x = (n01 & 7) << 4;
    const uint32_t b23b = n23 * 512, b23x = (n23 & 7) << 4;
    const uint32_t b_lk = ((lane >> 3) & 1) << 4;

    const int R0 = mhalf * 16 + (lane >> 2);                  // local rows R0, R0+8
    const int gc = (int)rank * 32 + ws * 8 + (lane & 3) * 2;  // global cells gc, gc+1

    // ---- zero h2(0) own slice (layer2 warps; ws-duplicates are idempotent)
    if (layer == 1){
        __nv_bfloat162 z; z.x = __float2bfloat16(0.f); z.y = z.x;
        #pragma unroll
        for (int rr = 0; rr < 2; ++rr){
            int r = m0 + R0 + rr * 8;
            *reinterpret_cast<__nv_bfloat162*>(&gh2[0][r * 256 + gc]) = z;
            *reinterpret_cast<__nv_bfloat162*>(&gh2[0][r * 256 + 128 + gc]) = z;
        }
    }

    float bia[4][2];
    #pragma unroll
    for (int g = 0; g < 4; ++g){
        bia[g][0] = bias[g * 128 + gc];
        bia[g][1] = bias[g * 128 + gc + 1];
    }

    float cst[4];                 // c-state: rows {R0, R0+8} x cells {gc, gc+1}
    #pragma unroll
    for (int j = 0; j < 4; ++j) cst[j] = 0.f;

    float acc[4][4];

    #define ACC_INIT()                                          \
        _Pragma("unroll")                                       \
        for (int g = 0; g < 4; ++g){                            \
            acc[g][0] = bia[g][0]; acc[g][1] = bia[g][1];       \
            acc[g][2] = bia[g][0]; acc[g][3] = bia[g][1];       \
        }

    // full K=128 GEMM onto acc: A m16 from (AHI, ALO), B rows at +BOFS bytes
    #define MMA8(AHI, ALO, BOFS)                                                       \
    {                                                                                  \
        _Pragma("unroll")                                                              \
        for (int ks = 0; ks < 8; ++ks){                                                \
            uint32_t kbA = (uint32_t)(ks * 32) + a_lk;                                 \
            uint32_t kbB = (uint32_t)(ks * 32) + (uint32_t)(BOFS) + b_lk;              \
            uint32_t ahi[4], alo[4], bh[8], bl[8];                                     \
            ldsm4(ahi[0], ahi[1], ahi[2], ahi[3], (AHI) + a_base + (kbA ^ a_xor));     \
            ldsm4(alo[0], alo[1], alo[2], alo[3], (ALO) + a_base + (kbA ^ a_xor));     \
            ldsm4(bh[0], bh[1], bh[2], bh[3], sbase + SM_BHI + b01b + (kbB ^ b01x));   \
            ldsm4(bh[4], bh[5], bh[6], bh[7], sbase + SM_BHI + b23b + (kbB ^ b23x));   \
            ldsm4(bl[0], bl[1], bl[2], bl[3], sbase + SM_BLO + b01b + (kbB ^ b01x));   \
            ldsm4(bl[4], bl[5], bl[6], bl[7], sbase + SM_BLO + b23b + (kbB ^ b23x));   \
            _Pragma("unroll")                                                          \
            for (int g = 0; g < 4; ++g){                                               \
                hmma(acc[g], ahi, bh[g*2], bh[g*2+1]);                                 \
                hmma(acc[g], ahi, bl[g*2], bl[g*2+1]);                                 \
                hmma(acc[g], alo, bh[g*2], bh[g*2+1]);                                 \
            }                                                                          \
        }                                                                              \
    }

    // issue a 16KB h-buffer readback with this layer's 256 threads
    #define ISSUE_H(DSTBASE, SRC)                                                     \
    {                                                                                 \
        _Pragma("unroll")                                                             \
        for (int i = 0; i < 4; ++i){                                                  \
            int idx = lt + i * 256;                                                   \
            int pl = idx >> 9, r = (idx >> 4) & 31, u = idx & 15;                     \
            cpa16((DSTBASE) + pl * 8192 + r * 256 + (((u ^ (r & 7)) << 4)),           \
                  &(SRC)[(m0 + r) * 256 + pl * 128 + u * 8]);                         \
        }                                                                             \
    }

    #define EPILOGUE(HV)                                                              \
        _Pragma("unroll")                                                             \
        for (int v = 0; v < 4; ++v){                                                  \
            float cn = fsig(acc[1][v]) * cst[v] + fsig(acc[0][v]) * ftanh_(acc[2][v]);\
            cst[v] = cn;                                                              \
            HV[v] = fsig(acc[3][v]) * ftanh_(cn);                                     \
        }

    const uint32_t H1A = sbase + SM_H1A, H1C = sbase + SM_H1C, H2b = sbase + SM_H2;

    // ---- prologue: layer1 computes h1(1) = E1(bias + x(0)·W); publish to gh1[1]
    cp_wait<0>();
    __syncthreads();
    if (layer == 0){
        ACC_INIT();
        MMA8(sbase + SM_X, sbase + SM_X + 8192, 0);
        float hv[4];
        EPILOGUE(hv);
        #pragma unroll
        for (int rr = 0; rr < 2; ++rr){
            int r = m0 + R0 + rr * 8;
            __nv_bfloat162 hh, ll;
            split1(hv[rr * 2 + 0], hh.x, ll.x);
            split1(hv[rr * 2 + 1], hh.y, ll.y);
            *reinterpret_cast<__nv_bfloat162*>(&gh1[1][r * 256 + gc]) = hh;
            *reinterpret_cast<__nv_bfloat162*>(&gh1[1][r * 256 + 128 + gc]) = ll;
        }
    }
    cl_arrive();     // B_{-1}: h1(1), h2(0) published

    for (int t = 0; t < TSTEPS; ++t){
        const int s = t & 1, ns = s ^ 1;
        const uint32_t Xrd = sbase + SM_X + ns * 16384;   // x(t+1)
        const uint32_t Xwr = sbase + SM_X + s * 16384;    // refill x(t+2)

        // ===== PRE-WAIT zone: barrier-independent work fills the skew window =====
        ACC_INIT();
        if (layer == 0){
            cp_wait<0>();                // all own prior groups retired (incl. x(t+1) refill)
            barn(1);                     // Xrd complete across all L1 threads
            if (t + 1 < TSTEPS){
                MMA8(Xrd, Xrd + 8192, 0);    // z1(t+1) += x(t+1)·W
            }
        }

        cl_wait();   // B_{t-1}: h1(t+1) [gh1[ns]] and h2(t) [gh2[s]] visible

        if (layer == 0){
            // ========= LAYER-1 post-wait =========
            ISSUE_H(H1A, gh1[ns]);           // h1(t+1) -> private copy
            cp_commit();
            if (t + 2 < TSTEPS){             // X refill x(t+2) -> slot s
                #pragma unroll
                for (int i = 0; i < 4; ++i){
                    int idx = lt + i * 256;
                    int pl = idx >> 9, r = (idx >> 4) & 31, u = idx & 15;
                    const __nv_bfloat16* sp = (pl ? gx_lo : gx_hi)
                        + ((size_t)(m0 + r) * TSTEPS + (t + 2)) * DDIM + u * 8;
                    cpa16(Xwr + pl * 8192 + r * 256 + (((u ^ (r & 7)) << 4)), sp);
                }
            }
            cp_commit();

            cp_wait<1>();                    // H1A done (mine); X refill still in flight
            barn(1);                         // H1A done (all L1 threads)
            MMA8(H1A, H1A + 8192, 256);      // z1(t+1) += h1(t+1)·U

            // E1 -> h1(t+2) -> gh1[s]
            float hv[4];
            EPILOGUE(hv);
            #pragma unroll
            for (int rr = 0; rr < 2; ++rr){
                int r = m0 + R0 + rr * 8;
                __nv_bfloat162 hh, ll;
                split1(hv[rr * 2 + 0], hh.x, ll.x);
                split1(hv[rr * 2 + 1], hh.y, ll.y);
                *reinterpret_cast<__nv_bfloat162*>(&gh1[s][r * 256 + gc]) = hh;
                *reinterpret_cast<__nv_bfloat162*>(&gh1[s][r * 256 + 128 + gc]) = ll;
            }
        } else {
            // ========= LAYER-2 post-wait =========
            ISSUE_H(H2b, gh2[s]);            // h2(t)
            cp_commit();
            ISSUE_H(H1C, gh1[ns]);           // h1(t+1) -> private copy
            cp_commit();

            cp_wait<1>();                    // H2b done (mine)
            barn(2);                         // H2b done (all L2 threads)
            MMA8(H2b, H2b + 8192, 256);      // z2 += h2(t)·U  (covers H1C)
            cp_wait<0>();                    // H1C done (mine)
            barn(2);
            MMA8(H1C, H1C + 8192, 0);        // z2 += h1(t+1)·W

            // residual h1(t+1) from H1C (hi+lo reconstruct)
            float res[4];
            #pragma unroll
            for (int rr = 0; rr < 2; ++rr){
                int rloc = R0 + rr * 8;
                uint32_t ho = (uint32_t)(rloc * 256
                            + ((((uint32_t)(gc >> 3) ^ (uint32_t)(rloc & 7))) << 4)
                            + ((2 * gc) & 15));
                __nv_bfloat162 hh = *reinterpret_cast<const __nv_bfloat162*>(smem + SM_H1C + ho);
                __nv_bfloat162 ll = *reinterpret_cast<const __nv_bfloat162*>(smem + SM_H1C + 8192 + ho);
                res[rr * 2 + 0] = __bfloat162float(hh.x) + __bfloat162float(ll.x);
                res[rr * 2 + 1] = __bfloat162float(hh.y) + __bfloat162float(ll.y);
            }
            float hv[4];
            EPILOGUE(hv);
            #pragma unroll
            for (int rr = 0; rr < 2; ++rr){
                int r = m0 + R0 + rr * 8;
                float h0 = hv[rr * 2 + 0] + res[rr * 2 + 0];   // + residual h1(t+1)
                float h1v = hv[rr * 2 + 1] + res[rr * 2 + 1];
                __nv_bfloat162 hh, ll;
                split1(h0, hh.x, ll.x);
                split1(h1v, hh.y, ll.y);
                *reinterpret_cast<__nv_bfloat162*>(&gh2[ns][r * 256 + gc]) = hh;
                *reinterpret_cast<__nv_bfloat162*>(&gh2[ns][r * 256 + 128 + gc]) = ll;
                float2 ov; ov.x = h0; ov.y = h1v;
                *reinterpret_cast<float2*>(&out[((size_t)r * TSTEPS + t) * DDIM + gc]) = ov;
            }
        }

        cl_arrive();     // B_t: h1(t+2) + h2(t+1) published
    }
    cl_wait();           // consume final arrive

    #undef EPILOGUE
    #undef ISSUE_H
    #undef MMA8
    #undef ACC_INIT
}

extern "C" void kernel_launch(void* const* d_in, const int* in_sizes, int n_in,
                              void* d_out, int out_size)
{
    const float* x    = (const float*)d_in[0];
    const float* W    = (const float*)d_in[1];
    const float* U    = (const float*)d_in[2];
    const float* bias = (const float*)d_in[3];
    // d_in[4] = seq_len: reference ignores it
    float* out = (float*)d_out;

    split_x_kernel<<<(BATCH * TSTEPS * DDIM / 4) / 256, 256>>>(x);

    cudaFuncSetAttribute(lstm_main_kernel,
                         cudaFuncAttributeMaxDynamicSharedMemorySize, SMEM_MAIN);
    lstm_main_kernel<<<128, THREADS, SMEM_MAIN>>>(W, U, bias, out);
}